// round 12
// baseline (speedup 1.0000x reference)
#include <cuda_runtime.h>
#include <cuda_fp16.h>
#include <math.h>
#include <stdint.h>

// Problem constants
#define Bb 16
#define Ll 128
#define Dd 512
#define Ff 1024
#define Mm 2048

// -------- device scratch (proven safe footprint) --------
__device__ __align__(16) float g_c1[Ll*16];
__device__ __align__(16) float g_c2[Ll*16];
__device__ __align__(16) float g_c3[Ll*16];
__device__ __align__(16) float g_Gg[256*Ff];
__device__ __align__(16) float g_Gu[256*Ff];
__device__ __align__(16) float g_Gd[256*Dd];
__device__ __align__(16) float g_ing[Ll*Ff];
__device__ __align__(16) float g_inu[Ll*Ff];
__device__ __align__(16) float g_ind[Ll*Dd];
__device__ __align__(16) float g_U[Mm*Ff];   // also reused as split-K partial for O
__device__ __align__(16) float g_V[Mm*Ff];
__device__ __align__(16) float g_H[Mm*Ff];
__device__ __align__(16) float g_O[Mm*Dd];

// ---------------- PTX helpers ----------------
__device__ __forceinline__ uint32_t smem_u32(const void* p) {
    uint32_t a;
    asm("{ .reg .u64 t; cvta.to.shared.u64 t, %1; cvt.u32.u64 %0, t; }" : "=r"(a) : "l"(p));
    return a;
}
__device__ __forceinline__ void ldsm4(uint32_t* r, uint32_t addr) {
    asm volatile("ldmatrix.sync.aligned.m8n8.x4.shared.b16 {%0,%1,%2,%3}, [%4];"
        : "=r"(r[0]), "=r"(r[1]), "=r"(r[2]), "=r"(r[3]) : "r"(addr));
}
__device__ __forceinline__ void ldsm4t(uint32_t* r, uint32_t addr) {
    asm volatile("ldmatrix.sync.aligned.m8n8.x4.trans.shared.b16 {%0,%1,%2,%3}, [%4];"
        : "=r"(r[0]), "=r"(r[1]), "=r"(r[2]), "=r"(r[3]) : "r"(addr));
}
__device__ __forceinline__ void mmaf16(float* c, const uint32_t* a, const uint32_t* b) {
    asm volatile("mma.sync.aligned.m16n8k16.row.col.f32.f16.f16.f32 "
        "{%0,%1,%2,%3}, {%4,%5,%6,%7}, {%8,%9}, {%0,%1,%2,%3};"
        : "+f"(c[0]), "+f"(c[1]), "+f"(c[2]), "+f"(c[3])
        : "r"(a[0]), "r"(a[1]), "r"(a[2]), "r"(a[3]), "r"(b[0]), "r"(b[1]));
}
__device__ __forceinline__ void sts16(uint32_t addr, uint4 v) {
    asm volatile("st.shared.v4.b32 [%0], {%1,%2,%3,%4};" ::
        "r"(addr), "r"(v.x), "r"(v.y), "r"(v.z), "r"(v.w) : "memory");
}
__device__ __forceinline__ void sts8(uint32_t addr, uint32_t x, uint32_t y) {
    asm volatile("st.shared.v2.b32 [%0], {%1,%2};" :: "r"(addr), "r"(x), "r"(y) : "memory");
}

// B: float4 -> 4 fp16 (8B), single matrix
__device__ __forceinline__ void cvtB_store4(float4 v, uint32_t addr) {
    __half2 h0 = __float22half2_rn(make_float2(v.x, v.y));
    __half2 h1 = __float22half2_rn(make_float2(v.z, v.w));
    sts8(addr, *(uint32_t*)&h0, *(uint32_t*)&h1);
}
// A: 8 scaled floats -> fp16 hi 16B + fp16 lo 16B
__device__ __forceinline__ void cvtA_store8(float4 va, float4 vb, float sc,
                                            uint32_t hiAddr, uint32_t loAddr) {
    va.x *= sc; va.y *= sc; va.z *= sc; va.w *= sc;
    vb.x *= sc; vb.y *= sc; vb.z *= sc; vb.w *= sc;
    __half2 h0 = __float22half2_rn(make_float2(va.x, va.y));
    __half2 h1 = __float22half2_rn(make_float2(va.z, va.w));
    __half2 h2 = __float22half2_rn(make_float2(vb.x, vb.y));
    __half2 h3 = __float22half2_rn(make_float2(vb.z, vb.w));
    float2 f0 = __half22float2(h0);
    float2 f1 = __half22float2(h1);
    float2 f2 = __half22float2(h2);
    float2 f3 = __half22float2(h3);
    __half2 l0 = __float22half2_rn(make_float2(va.x - f0.x, va.y - f0.y));
    __half2 l1 = __float22half2_rn(make_float2(va.z - f1.x, va.w - f1.y));
    __half2 l2 = __float22half2_rn(make_float2(vb.x - f2.x, vb.y - f2.y));
    __half2 l3 = __float22half2_rn(make_float2(vb.z - f3.x, vb.w - f3.y));
    sts16(hiAddr, make_uint4(*(uint32_t*)&h0, *(uint32_t*)&h1, *(uint32_t*)&h2, *(uint32_t*)&h3));
    sts16(loAddr, make_uint4(*(uint32_t*)&l0, *(uint32_t*)&l1, *(uint32_t*)&l2, *(uint32_t*)&l3));
}

// ---------------- softmax ----------------
__global__ void softmax_kernel(const float* __restrict__ t1,
                               const float* __restrict__ t2,
                               const float* __restrict__ t3) {
    const float* src = (blockIdx.x == 0) ? t1 : (blockIdx.x == 1) ? t2 : t3;
    float* dst = (blockIdx.x == 0) ? g_c1 : (blockIdx.x == 1) ? g_c2 : g_c3;
    int l = threadIdx.x;
    float v[16];
    float mx = -1e30f;
#pragma unroll
    for (int k = 0; k < 16; k++) { v[k] = src[l*16 + k]; mx = fmaxf(mx, v[k]); }
    float s = 0.f;
#pragma unroll
    for (int k = 0; k < 16; k++) { v[k] = expf(v[k] - mx); s += v[k]; }
    float inv = 1.f / s;
#pragma unroll
    for (int k = 0; k < 16; k++) dst[l*16 + k] = v[k] * inv;
}

// ---------------- Gram ----------------
__global__ void gram_kernel(const float* __restrict__ Wg,
                            const float* __restrict__ Wu,
                            const float* __restrict__ Wd) {
    int w = blockIdx.y;
    const float* W; float* G; int R, C;
    if (w == 0)      { W = Wg; G = g_Gg; R = Dd; C = Ff; }
    else if (w == 1) { W = Wu; G = g_Gu; R = Dd; C = Ff; }
    else             { W = Wd; G = g_Gd; R = Ff; C = Dd; }
    int c0 = blockIdx.x * 32;
    if (c0 >= C) return;

    __shared__ __align__(16) float s[16][8][32];
    int t = threadIdx.x;
    int cc = t & 31;
    int pg = t >> 5;
    float acc[32];
#pragma unroll
    for (int i = 0; i < 32; i++) acc[i] = 0.f;

    for (int r0 = 0; r0 < R; r0 += 8) {
        __syncthreads();
#pragma unroll
        for (int j = 0; j < 16; j++) {
            int idx = j * 256 + t;
            int lc = idx & 31, rr = (idx >> 5) & 7, k = idx >> 8;
            s[k][rr][lc] = W[(size_t)k * R * C + (size_t)(r0 + rr) * C + c0 + lc];
        }
        __syncthreads();
#pragma unroll
        for (int rr = 0; rr < 8; rr++) {
            float wv[16];
#pragma unroll
            for (int k = 0; k < 16; k++) wv[k] = s[k][rr][cc];
            float a0 = s[(pg << 1) + 0][rr][cc];
            float a1 = s[(pg << 1) + 1][rr][cc];
#pragma unroll
            for (int pp = 0; pp < 16; pp++) acc[pp]      += a0 * wv[pp];
#pragma unroll
            for (int pp = 0; pp < 16; pp++) acc[16 + pp] += a1 * wv[pp];
        }
    }
#pragma unroll
    for (int pp = 0; pp < 32; pp++) {
        int p = ((pg << 1) + (pp >> 4)) * 16 + (pp & 15);
        G[(size_t)p * C + c0 + cc] = acc[pp];
    }
}

// ---------------- inverse norms: 8 tokens per block ----------------
__global__ void norm_kernel() {
    int w = blockIdx.z;
    int l0 = blockIdx.y * 8;
    const float* G; const float* coef; float* out; int C;
    if (w == 0)      { G = g_Gg; coef = g_c1; out = g_ing; C = Ff; }
    else if (w == 1) { G = g_Gu; coef = g_c2; out = g_inu; C = Ff; }
    else             { G = g_Gd; coef = g_c3; out = g_ind; C = Dd; }
    int c = blockIdx.x * 128 + threadIdx.x;
    if (c >= C) return;   // guard: down plane has C=512

    __shared__ float w2[8][256];
#pragma unroll
    for (int i = 0; i < 16; i++) {
        int idx = threadIdx.x * 16 + i;
        int li = idx >> 8, p = idx & 255;
        w2[li][p] = coef[(l0 + li) * 16 + (p >> 4)] * coef[(l0 + li) * 16 + (p & 15)];
    }
    __syncthreads();

    float acc[8];
#pragma unroll
    for (int i = 0; i < 8; i++) acc[i] = 0.f;
#pragma unroll 4
    for (int p = 0; p < 256; p++) {
        float g = G[(size_t)p * C + c];
#pragma unroll
        for (int i = 0; i < 8; i++) acc[i] += w2[i][p] * g;
    }
#pragma unroll
    for (int i = 0; i < 8; i++)
        out[(l0 + i) * C + c] = 1.f / fmaxf(sqrtf(fmaxf(acc[i], 0.f)), 1e-12f);
}

// ---------------- UV GEMM (unchanged from R11): fp16 2-MMA, 512 thr, reg prefetch ----------------
template<int BN>
__global__ void __launch_bounds__(512, 1) gemm7(
    const float* __restrict__ A0,
    const float* __restrict__ Bw0, const float* __restrict__ Bw1,
    int which, int Ka, int ksegShift, int Ktot, int Nglob)
{
    constexpr int WN = BN / 4;
    constexpr int NF = WN / 8;
    constexpr int AMB = 128 * 80;
    constexpr int BSTRIDE = BN * 2 + 16;
    constexpr int BMB = 32 * BSTRIDE;
    constexpr int QPT4 = BN / 64;

    __shared__ __align__(128) char smem_raw[2 * AMB + BMB];
    uint32_t sA_hi = smem_u32(smem_raw);
    uint32_t sA_lo = sA_hi + AMB;
    uint32_t sB    = sA_hi + 2 * AMB;

    const float* coef; float* Cout; const float* Ap; const float* Bw;
    if (which == 0) {
        Ap = A0;
        if (blockIdx.z == 0) { coef = g_c1; Bw = Bw0; Cout = g_U; }
        else                 { coef = g_c2; Bw = Bw1; Cout = g_V; }
    } else {
        Ap = g_H; coef = g_c3; Bw = Bw0; Cout = g_O;
    }

    int t = threadIdx.x, lane = t & 31, warp = t >> 5;
    int wm = warp & 3, wn = warp >> 2;
    int m0 = blockIdx.y * 128, n0 = blockIdx.x * BN;

    int arow = t >> 2, aq = t & 3;
    const float* aRow = Ap + (size_t)(m0 + arow) * Ka + aq * 8;
    const float* crow = coef + ((m0 + arow) & 127) * 16;
    uint32_t aoff = (uint32_t)arow * 80 + aq * 16;

    int krow = t >> 4;
    int bq = t & 15;
    const float* bRowBase = Bw + (size_t)krow * Nglob + n0;
    uint32_t bRowOff = (uint32_t)krow * BSTRIDE;

    float acc[2][NF][4];
#pragma unroll
    for (int f = 0; f < 2; f++)
#pragma unroll
        for (int g = 0; g < NF; g++)
#pragma unroll
            for (int j = 0; j < 4; j++) acc[f][g][j] = 0.f;

    int nit = Ktot >> 5;

    float4 pa0, pa1, pbv[QPT4];
    float psc;
    {
        psc = crow[0];
        pa0 = *(const float4*)(aRow + 0);
        pa1 = *(const float4*)(aRow + 4);
#pragma unroll
        for (int j = 0; j < QPT4; j++)
            pbv[j] = *(const float4*)(bRowBase + (bq + 16 * j) * 4);
    }

    for (int it = 0; it < nit; it++) {
        cvtA_store8(pa0, pa1, psc, sA_hi + aoff, sA_lo + aoff);
#pragma unroll
        for (int j = 0; j < QPT4; j++)
            cvtB_store4(pbv[j], sB + bRowOff + (bq + 16 * j) * 8);
        __syncthreads();

        if (it + 1 < nit) {
            int ktn = (it + 1) << 5;
            psc = crow[ktn >> ksegShift];
            const float* ar = aRow + (ktn & (Ka - 1));
            pa0 = *(const float4*)(ar + 0);
            pa1 = *(const float4*)(ar + 4);
            const float* br = bRowBase + (size_t)ktn * Nglob;
#pragma unroll
            for (int j = 0; j < QPT4; j++)
                pbv[j] = *(const float4*)(br + (bq + 16 * j) * 4);
        }

#pragma unroll
        for (int ks = 0; ks < 2; ks++) {
            uint32_t BF[NF][2];
            uint32_t brow = (uint32_t)(ks * 16 + (lane & 15)) * BSTRIDE;
#pragma unroll
            for (int j = 0; j < NF / 2; j++) {
                uint32_t coff = (uint32_t)(wn * WN + j * 16 + ((lane >> 4) & 1) * 8) * 2;
                uint32_t r[4];
                ldsm4t(r, sB + brow + coff);
                BF[2*j][0] = r[0]; BF[2*j][1] = r[1];
                BF[2*j+1][0] = r[2]; BF[2*j+1][1] = r[3];
            }
            uint32_t acolB = (uint32_t)ks * 32 + ((lane >> 4) & 1) * 16;
            {
                uint32_t AF[2][4];
#pragma unroll
                for (int f = 0; f < 2; f++) {
                    uint32_t roff = (uint32_t)(wm * 32 + f * 16 + (lane & 15)) * 80 + acolB;
                    ldsm4(AF[f], sA_hi + roff);
                }
#pragma unroll
                for (int f = 0; f < 2; f++)
#pragma unroll
                    for (int g = 0; g < NF; g++)
                        mmaf16(acc[f][g], AF[f], BF[g]);
            }
            {
                uint32_t AF[2][4];
#pragma unroll
                for (int f = 0; f < 2; f++) {
                    uint32_t roff = (uint32_t)(wm * 32 + f * 16 + (lane & 15)) * 80 + acolB;
                    ldsm4(AF[f], sA_lo + roff);
                }
#pragma unroll
                for (int f = 0; f < 2; f++)
#pragma unroll
                    for (int g = 0; g < NF; g++)
                        mmaf16(acc[f][g], AF[f], BF[g]);
            }
        }
        __syncthreads();
    }

#pragma unroll
    for (int f = 0; f < 2; f++) {
#pragma unroll
        for (int g = 0; g < NF; g++) {
            int r0 = m0 + wm * 32 + f * 16 + (lane >> 2);
            int col = n0 + wn * WN + g * 8 + (lane & 3) * 2;
            float* p = Cout + (size_t)r0 * Nglob + col;
            *(float2*)p = make_float2(acc[f][g][0], acc[f][g][1]);
            *(float2*)(p + 8 * (size_t)Nglob) = make_float2(acc[f][g][2], acc[f][g][3]);
        }
    }
}

// ---------------- down GEMM: BK=64, split-K=2 (z), fp16 2-MMA, 512 threads ----------------
// O_partial[z][M=2048, 512] = (c3 . h)[:, z*8192:(z+1)*8192] @ Wd[z*8192:(z+1)*8192, :]
// z=0 -> g_O, z=1 -> g_U (reused as scratch; g_U dead after h_kernel).
// BM=128, BN=64, BK=64. A smem rows 144B (conflict-free), B rows 144B. 46080B static.
__global__ void __launch_bounds__(512, 1) gemm8(const float* __restrict__ Bw)
{
    constexpr int WN = 16;
    constexpr int NF = 2;
    constexpr int ASTRIDE = 144;            // 64 fp16 = 128B + 16 pad
    constexpr int AMB = 128 * ASTRIDE;      // 18432 per matrix
    constexpr int BSTRIDE = 144;            // 64 fp16 + pad
    constexpr int BMB = 64 * BSTRIDE;       // 9216

    __shared__ __align__(128) char smem_raw[2 * AMB + BMB];  // 46080
    uint32_t sA_hi = smem_u32(smem_raw);
    uint32_t sA_lo = sA_hi + AMB;
    uint32_t sB    = sA_hi + 2 * AMB;

    const float* Ap = g_H;
    const float* coef = g_c3;
    float* Cout = (blockIdx.z == 0) ? g_O : g_U;
    int kglob0 = blockIdx.z * 8192;

    int t = threadIdx.x, lane = t & 31, warp = t >> 5;
    int wm = warp & 3, wn = warp >> 2;
    int m0 = blockIdx.y * 128, n0 = blockIdx.x * 64;

    // A staging: 4 threads per row, 16 floats each
    int arow = t >> 2, aq = t & 3;
    const float* aRow = Ap + (size_t)(m0 + arow) * 1024 + aq * 16;
    const float* crow = coef + ((m0 + arow) & 127) * 16;
    uint32_t aoff = (uint32_t)arow * ASTRIDE + aq * 32;

    // B staging: 8 threads per k-row (64 rows), 2 float4 each
    int krow = t >> 3;
    int bq = t & 7;
    const float* bRowBase = Bw + (size_t)(kglob0 + krow) * 512 + n0;
    uint32_t bRowOff = (uint32_t)krow * BSTRIDE;

    float acc[2][NF][4];
#pragma unroll
    for (int f = 0; f < 2; f++)
#pragma unroll
        for (int g = 0; g < NF; g++)
#pragma unroll
            for (int j = 0; j < 4; j++) acc[f][g][j] = 0.f;

    const int nit = 128;   // 8192 / 64

    // prologue
    float4 pa0, pa1, pa2, pa3, pb0, pb1;
    float psc;
    {
        int ktg = kglob0;
        psc = crow[ktg >> 10];
        const float* ar = aRow + (ktg & 1023);
        pa0 = *(const float4*)(ar + 0);
        pa1 = *(const float4*)(ar + 4);
        pa2 = *(const float4*)(ar + 8);
        pa3 = *(const float4*)(ar + 12);
        pb0 = *(const float4*)(bRowBase + bq * 4);
        pb1 = *(const float4*)(bRowBase + (bq + 8) * 4);
    }

    for (int it = 0; it < nit; it++) {
        cvtA_store8(pa0, pa1, psc, sA_hi + aoff,      sA_lo + aoff);
        cvtA_store8(pa2, pa3, psc, sA_hi + aoff + 16, sA_lo + aoff + 16);
        cvtB_store4(pb0, sB + bRowOff + bq * 8);
        cvtB_store4(pb1, sB + bRowOff + (bq + 8) * 8);
        __syncthreads();

        if (it + 1 < nit) {
            int ktg = kglob0 + ((it + 1) << 6);
            psc = crow[ktg >> 10];
            const float* ar = aRow + (ktg & 1023);
            pa0 = *(const float4*)(ar + 0);
            pa1 = *(const float4*)(ar + 4);
            pa2 = *(const float4*)(ar + 8);
            pa3 = *(const float4*)(ar + 12);
            const float* br = bRowBase + (size_t)((it + 1) << 6) * 512;
            pb0 = *(const float4*)(br + bq * 4);
            pb1 = *(const float4*)(br + (bq + 8) * 4);
        }

#pragma unroll
        for (int ks = 0; ks < 4; ks++) {
            uint32_t BF[NF][2];
            uint32_t brow = (uint32_t)(ks * 16 + (lane & 15)) * BSTRIDE;
            {
                uint32_t coff = (uint32_t)(wn * WN + ((lane >> 4) & 1) * 8) * 2;
                uint32_t r[4];
                ldsm4t(r, sB + brow + coff);
                BF[0][0] = r[0]; BF[0][1] = r[1];
                BF[1][0] = r[2]; BF[1][1] = r[3];
            }
            uint32_t acolB = (uint32_t)ks * 32 + ((lane >> 4) & 1) * 16;
            {
                uint32_t AF[2][4];
#pragma unroll
                for (int f = 0; f < 2; f++) {
                    uint32_t roff = (uint32_t)(wm * 32 + f * 16 + (lane & 15)) * ASTRIDE + acolB;
                    ldsm4(AF[f], sA_hi + roff);
                }
#pragma unroll
                for (int f = 0; f < 2; f++)
#pragma unroll
                    for (int g = 0; g < NF; g++)
                        mmaf16(acc[f][g], AF[f], BF[g]);
            }
            {
                uint32_t AF[2][4];
#pragma unroll
                for (int f = 0; f < 2; f++) {
                    uint32_t roff = (uint32_t)(wm * 32 + f * 16 + (lane & 15)) * ASTRIDE + acolB;
                    ldsm4(AF[f], sA_lo + roff);
                }
#pragma unroll
                for (int f = 0; f < 2; f++)
#pragma unroll
                    for (int g = 0; g < NF; g++)
                        mmaf16(acc[f][g], AF[f], BF[g]);
            }
        }
        __syncthreads();
    }

    // epilogue
#pragma unroll
    for (int f = 0; f < 2; f++) {
#pragma unroll
        for (int g = 0; g < NF; g++) {
            int r0 = m0 + wm * 32 + f * 16 + (lane >> 2);
            int col = n0 + wn * WN + g * 8 + (lane & 3) * 2;
            float* p = Cout + (size_t)r0 * 512 + col;
            *(float2*)p = make_float2(acc[f][g][0], acc[f][g][1]);
            *(float2*)(p + 8 * 512) = make_float2(acc[f][g][2], acc[f][g][3]);
        }
    }
}

// ---------------- elementwise h ----------------
__global__ void h_kernel(const float* __restrict__ usp, const float* __restrict__ vsp) {
    const float SQRT_D = 22.62741699796952f;
    int i4 = blockIdx.x * blockDim.x + threadIdx.x;
    if (i4 >= Mm * Ff / 4) return;
    int m  = i4 >> 8;
    int f  = (i4 & 255) * 4;
    int l  = m & 127;

    float4 u  = *(const float4*)(g_U   + (size_t)m * Ff + f);
    float4 v  = *(const float4*)(g_V   + (size_t)m * Ff + f);
    float4 ig = *(const float4*)(g_ing + (size_t)l * Ff + f);
    float4 iu = *(const float4*)(g_inu + (size_t)l * Ff + f);
    float4 us = *(const float4*)(usp + f);
    float4 vs = *(const float4*)(vsp + f);

    float4 h;
    { float uu = u.x * ig.x, vv = v.x * iu.x; float zz = fabsf(vs.x) * SQRT_D * vv;
      h.x = (zz / (1.f + expf(-zz))) * (fabsf(us.x) * uu); }
    { float uu = u.y * ig.y, vv = v.y * iu.y; float zz = fabsf(vs.y) * SQRT_D * vv;
      h.y = (zz / (1.f + expf(-zz))) * (fabsf(us.y) * uu); }
    { float uu = u.z * ig.z, vv = v.z * iu.z; float zz = fabsf(vs.z) * SQRT_D * vv;
      h.z = (zz / (1.f + expf(-zz))) * (fabsf(us.z) * uu); }
    { float uu = u.w * ig.w, vv = v.w * iu.w; float zz = fabsf(vs.w) * SQRT_D * vv;
      h.w = (zz / (1.f + expf(-zz))) * (fabsf(us.w) * uu); }
    *(float4*)(g_H + (size_t)m * Ff + f) = h;
}

// ---------------- final: sum split-K partials, apply down-norm, row L2 normalize ----------------
__global__ void out_kernel(float* __restrict__ out) {
    int m = blockIdx.x;
    int t = threadIdx.x;
    int l = m & 127;

    float4 o  = *(const float4*)(g_O + (size_t)m * Dd + t * 4);
    float4 o2 = *(const float4*)(g_U + (size_t)m * Dd + t * 4);   // split-K partial 1
    float4 iv = *(const float4*)(g_ind + (size_t)l * Dd + t * 4);
    o.x = (o.x + o2.x) * iv.x;
    o.y = (o.y + o2.y) * iv.y;
    o.z = (o.z + o2.z) * iv.z;
    o.w = (o.w + o2.w) * iv.w;

    float ss = o.x*o.x + o.y*o.y + o.z*o.z + o.w*o.w;
#pragma unroll
    for (int off = 16; off > 0; off >>= 1)
        ss += __shfl_xor_sync(0xffffffffu, ss, off);

    __shared__ float ws[4];
    if ((t & 31) == 0) ws[t >> 5] = ss;
    __syncthreads();
    float tot = ws[0] + ws[1] + ws[2] + ws[3];
    float sc = 1.f / fmaxf(sqrtf(tot), 1e-12f);

    o.x *= sc; o.y *= sc; o.z *= sc; o.w *= sc;
    *(float4*)(out + (size_t)m * Dd + t * 4) = o;
}

// ---------------- launch ----------------
extern "C" void kernel_launch(void* const* d_in, const int* in_sizes, int n_in,
                              void* d_out, int out_size) {
    const float* x   = (const float*)d_in[0];
    const float* Wg  = (const float*)d_in[1];
    const float* Wu  = (const float*)d_in[2];
    const float* Wd  = (const float*)d_in[3];
    const float* t1  = (const float*)d_in[4];
    const float* t2  = (const float*)d_in[5];
    const float* t3  = (const float*)d_in[6];
    const float* usp = (const float*)d_in[7];
    const float* vsp = (const float*)d_in[8];
    float* out = (float*)d_out;

    softmax_kernel<<<3, 128>>>(t1, t2, t3);
    gram_kernel<<<dim3(32, 3), 256>>>(Wg, Wu, Wd);
    norm_kernel<<<dim3(8, 16, 3), 128>>>();

    // U and V fused (z=0 -> U, z=1 -> V): BN=256, 128 blocks, 512 threads
    gemm7<256><<<dim3(4, 16, 2), 512>>>(x, Wg, Wu, 0, 512, 9, 8192, 1024);
    // h = silu(vs*v) * (us*u)  (consumes g_U/g_V, frees g_U for reuse)
    h_kernel<<<2048, 256>>>(usp, vsp);
    // O = (c3 . h) @ Wd: BK=64, split-K=2 (z=0 -> g_O, z=1 -> g_U scratch)
    gemm8<<<dim3(8, 16, 2), 512>>>(Wd);
    // final: sum partials + normalize
    out_kernel<<<2048, 128>>>(out);
}

// round 13
// speedup vs baseline: 1.1968x; 1.1968x over previous
#include <cuda_runtime.h>
#include <cuda_fp16.h>
#include <math.h>
#include <stdint.h>

// Problem constants
#define Bb 16
#define Ll 128
#define Dd 512
#define Ff 1024
#define Mm 2048

// -------- device scratch (proven safe footprint) --------
__device__ __align__(16) float g_c1[Ll*16];
__device__ __align__(16) float g_c2[Ll*16];
__device__ __align__(16) float g_c3[Ll*16];
__device__ __align__(16) float g_Gg[256*Ff];
__device__ __align__(16) float g_Gu[256*Ff];
__device__ __align__(16) float g_Gd[256*Dd];
__device__ __align__(16) float g_ing[Ll*Ff];
__device__ __align__(16) float g_inu[Ll*Ff];
__device__ __align__(16) float g_ind[Ll*Dd];
__device__ __align__(16) float g_U[Mm*Ff];   // reused: split-K partials 1,2 for O
__device__ __align__(16) float g_V[Mm*Ff];   // reused: split-K partial 3 for O
__device__ __align__(16) float g_H[Mm*Ff];
__device__ __align__(16) float g_O[Mm*Dd];   // split-K partial 0

// ---------------- PTX helpers ----------------
__device__ __forceinline__ uint32_t smem_u32(const void* p) {
    uint32_t a;
    asm("{ .reg .u64 t; cvta.to.shared.u64 t, %1; cvt.u32.u64 %0, t; }" : "=r"(a) : "l"(p));
    return a;
}
__device__ __forceinline__ void ldsm4(uint32_t* r, uint32_t addr) {
    asm volatile("ldmatrix.sync.aligned.m8n8.x4.shared.b16 {%0,%1,%2,%3}, [%4];"
        : "=r"(r[0]), "=r"(r[1]), "=r"(r[2]), "=r"(r[3]) : "r"(addr));
}
__device__ __forceinline__ void ldsm4t(uint32_t* r, uint32_t addr) {
    asm volatile("ldmatrix.sync.aligned.m8n8.x4.trans.shared.b16 {%0,%1,%2,%3}, [%4];"
        : "=r"(r[0]), "=r"(r[1]), "=r"(r[2]), "=r"(r[3]) : "r"(addr));
}
__device__ __forceinline__ void mmaf16(float* c, const uint32_t* a, const uint32_t* b) {
    asm volatile("mma.sync.aligned.m16n8k16.row.col.f32.f16.f16.f32 "
        "{%0,%1,%2,%3}, {%4,%5,%6,%7}, {%8,%9}, {%0,%1,%2,%3};"
        : "+f"(c[0]), "+f"(c[1]), "+f"(c[2]), "+f"(c[3])
        : "r"(a[0]), "r"(a[1]), "r"(a[2]), "r"(a[3]), "r"(b[0]), "r"(b[1]));
}
__device__ __forceinline__ void sts16(uint32_t addr, uint4 v) {
    asm volatile("st.shared.v4.b32 [%0], {%1,%2,%3,%4};" ::
        "r"(addr), "r"(v.x), "r"(v.y), "r"(v.z), "r"(v.w) : "memory");
}
__device__ __forceinline__ void sts8(uint32_t addr, uint32_t x, uint32_t y) {
    asm volatile("st.shared.v2.b32 [%0], {%1,%2};" :: "r"(addr), "r"(x), "r"(y) : "memory");
}

// B: float4 -> 4 fp16 (8B), single matrix
__device__ __forceinline__ void cvtB_store4(float4 v, uint32_t addr) {
    __half2 h0 = __float22half2_rn(make_float2(v.x, v.y));
    __half2 h1 = __float22half2_rn(make_float2(v.z, v.w));
    sts8(addr, *(uint32_t*)&h0, *(uint32_t*)&h1);
}
// A: 8 scaled floats -> fp16 hi 16B + fp16 lo 16B
__device__ __forceinline__ void cvtA_store8(float4 va, float4 vb, float sc,
                                            uint32_t hiAddr, uint32_t loAddr) {
    va.x *= sc; va.y *= sc; va.z *= sc; va.w *= sc;
    vb.x *= sc; vb.y *= sc; vb.z *= sc; vb.w *= sc;
    __half2 h0 = __float22half2_rn(make_float2(va.x, va.y));
    __half2 h1 = __float22half2_rn(make_float2(va.z, va.w));
    __half2 h2 = __float22half2_rn(make_float2(vb.x, vb.y));
    __half2 h3 = __float22half2_rn(make_float2(vb.z, vb.w));
    float2 f0 = __half22float2(h0);
    float2 f1 = __half22float2(h1);
    float2 f2 = __half22float2(h2);
    float2 f3 = __half22float2(h3);
    __half2 l0 = __float22half2_rn(make_float2(va.x - f0.x, va.y - f0.y));
    __half2 l1 = __float22half2_rn(make_float2(va.z - f1.x, va.w - f1.y));
    __half2 l2 = __float22half2_rn(make_float2(vb.x - f2.x, vb.y - f2.y));
    __half2 l3 = __float22half2_rn(make_float2(vb.z - f3.x, vb.w - f3.y));
    sts16(hiAddr, make_uint4(*(uint32_t*)&h0, *(uint32_t*)&h1, *(uint32_t*)&h2, *(uint32_t*)&h3));
    sts16(loAddr, make_uint4(*(uint32_t*)&l0, *(uint32_t*)&l1, *(uint32_t*)&l2, *(uint32_t*)&l3));
}

// ---------------- softmax ----------------
__global__ void softmax_kernel(const float* __restrict__ t1,
                               const float* __restrict__ t2,
                               const float* __restrict__ t3) {
    const float* src = (blockIdx.x == 0) ? t1 : (blockIdx.x == 1) ? t2 : t3;
    float* dst = (blockIdx.x == 0) ? g_c1 : (blockIdx.x == 1) ? g_c2 : g_c3;
    int l = threadIdx.x;
    float v[16];
    float mx = -1e30f;
#pragma unroll
    for (int k = 0; k < 16; k++) { v[k] = src[l*16 + k]; mx = fmaxf(mx, v[k]); }
    float s = 0.f;
#pragma unroll
    for (int k = 0; k < 16; k++) { v[k] = expf(v[k] - mx); s += v[k]; }
    float inv = 1.f / s;
#pragma unroll
    for (int k = 0; k < 16; k++) dst[l*16 + k] = v[k] * inv;
}

// ---------------- Gram ----------------
__global__ void gram_kernel(const float* __restrict__ Wg,
                            const float* __restrict__ Wu,
                            const float* __restrict__ Wd) {
    int w = blockIdx.y;
    const float* W; float* G; int R, C;
    if (w == 0)      { W = Wg; G = g_Gg; R = Dd; C = Ff; }
    else if (w == 1) { W = Wu; G = g_Gu; R = Dd; C = Ff; }
    else             { W = Wd; G = g_Gd; R = Ff; C = Dd; }
    int c0 = blockIdx.x * 32;
    if (c0 >= C) return;

    __shared__ __align__(16) float s[16][8][32];
    int t = threadIdx.x;
    int cc = t & 31;
    int pg = t >> 5;
    float acc[32];
#pragma unroll
    for (int i = 0; i < 32; i++) acc[i] = 0.f;

    for (int r0 = 0; r0 < R; r0 += 8) {
        __syncthreads();
#pragma unroll
        for (int j = 0; j < 16; j++) {
            int idx = j * 256 + t;
            int lc = idx & 31, rr = (idx >> 5) & 7, k = idx >> 8;
            s[k][rr][lc] = W[(size_t)k * R * C + (size_t)(r0 + rr) * C + c0 + lc];
        }
        __syncthreads();
#pragma unroll
        for (int rr = 0; rr < 8; rr++) {
            float wv[16];
#pragma unroll
            for (int k = 0; k < 16; k++) wv[k] = s[k][rr][cc];
            float a0 = s[(pg << 1) + 0][rr][cc];
            float a1 = s[(pg << 1) + 1][rr][cc];
#pragma unroll
            for (int pp = 0; pp < 16; pp++) acc[pp]      += a0 * wv[pp];
#pragma unroll
            for (int pp = 0; pp < 16; pp++) acc[16 + pp] += a1 * wv[pp];
        }
    }
#pragma unroll
    for (int pp = 0; pp < 32; pp++) {
        int p = ((pg << 1) + (pp >> 4)) * 16 + (pp & 15);
        G[(size_t)p * C + c0 + cc] = acc[pp];
    }
}

// ---------------- inverse norms: 8 tokens per block ----------------
__global__ void norm_kernel() {
    int w = blockIdx.z;
    int l0 = blockIdx.y * 8;
    const float* G; const float* coef; float* out; int C;
    if (w == 0)      { G = g_Gg; coef = g_c1; out = g_ing; C = Ff; }
    else if (w == 1) { G = g_Gu; coef = g_c2; out = g_inu; C = Ff; }
    else             { G = g_Gd; coef = g_c3; out = g_ind; C = Dd; }
    int c = blockIdx.x * 128 + threadIdx.x;
    if (c >= C) return;   // guard: down plane has C=512

    __shared__ float w2[8][256];
#pragma unroll
    for (int i = 0; i < 16; i++) {
        int idx = threadIdx.x * 16 + i;
        int li = idx >> 8, p = idx & 255;
        w2[li][p] = coef[(l0 + li) * 16 + (p >> 4)] * coef[(l0 + li) * 16 + (p & 15)];
    }
    __syncthreads();

    float acc[8];
#pragma unroll
    for (int i = 0; i < 8; i++) acc[i] = 0.f;
#pragma unroll 4
    for (int p = 0; p < 256; p++) {
        float g = G[(size_t)p * C + c];
#pragma unroll
        for (int i = 0; i < 8; i++) acc[i] += w2[i][p] * g;
    }
#pragma unroll
    for (int i = 0; i < 8; i++)
        out[(l0 + i) * C + c] = 1.f / fmaxf(sqrtf(fmaxf(acc[i], 0.f)), 1e-12f);
}

// ---------------- UV GEMM (unchanged, proven): fp16 2-MMA, 512 thr, reg prefetch ----------------
template<int BN>
__global__ void __launch_bounds__(512, 1) gemm7(
    const float* __restrict__ A0,
    const float* __restrict__ Bw0, const float* __restrict__ Bw1,
    int which, int Ka, int ksegShift, int Ktot, int Nglob)
{
    constexpr int WN = BN / 4;
    constexpr int NF = WN / 8;
    constexpr int AMB = 128 * 80;
    constexpr int BSTRIDE = BN * 2 + 16;
    constexpr int BMB = 32 * BSTRIDE;
    constexpr int QPT4 = BN / 64;

    __shared__ __align__(128) char smem_raw[2 * AMB + BMB];
    uint32_t sA_hi = smem_u32(smem_raw);
    uint32_t sA_lo = sA_hi + AMB;
    uint32_t sB    = sA_hi + 2 * AMB;

    const float* coef; float* Cout; const float* Ap; const float* Bw;
    if (which == 0) {
        Ap = A0;
        if (blockIdx.z == 0) { coef = g_c1; Bw = Bw0; Cout = g_U; }
        else                 { coef = g_c2; Bw = Bw1; Cout = g_V; }
    } else {
        Ap = g_H; coef = g_c3; Bw = Bw0; Cout = g_O;
    }

    int t = threadIdx.x, lane = t & 31, warp = t >> 5;
    int wm = warp & 3, wn = warp >> 2;
    int m0 = blockIdx.y * 128, n0 = blockIdx.x * BN;

    int arow = t >> 2, aq = t & 3;
    const float* aRow = Ap + (size_t)(m0 + arow) * Ka + aq * 8;
    const float* crow = coef + ((m0 + arow) & 127) * 16;
    uint32_t aoff = (uint32_t)arow * 80 + aq * 16;

    int krow = t >> 4;
    int bq = t & 15;
    const float* bRowBase = Bw + (size_t)krow * Nglob + n0;
    uint32_t bRowOff = (uint32_t)krow * BSTRIDE;

    float acc[2][NF][4];
#pragma unroll
    for (int f = 0; f < 2; f++)
#pragma unroll
        for (int g = 0; g < NF; g++)
#pragma unroll
            for (int j = 0; j < 4; j++) acc[f][g][j] = 0.f;

    int nit = Ktot >> 5;

    float4 pa0, pa1, pbv[QPT4];
    float psc;
    {
        psc = crow[0];
        pa0 = *(const float4*)(aRow + 0);
        pa1 = *(const float4*)(aRow + 4);
#pragma unroll
        for (int j = 0; j < QPT4; j++)
            pbv[j] = *(const float4*)(bRowBase + (bq + 16 * j) * 4);
    }

    for (int it = 0; it < nit; it++) {
        cvtA_store8(pa0, pa1, psc, sA_hi + aoff, sA_lo + aoff);
#pragma unroll
        for (int j = 0; j < QPT4; j++)
            cvtB_store4(pbv[j], sB + bRowOff + (bq + 16 * j) * 8);
        __syncthreads();

        if (it + 1 < nit) {
            int ktn = (it + 1) << 5;
            psc = crow[ktn >> ksegShift];
            const float* ar = aRow + (ktn & (Ka - 1));
            pa0 = *(const float4*)(ar + 0);
            pa1 = *(const float4*)(ar + 4);
            const float* br = bRowBase + (size_t)ktn * Nglob;
#pragma unroll
            for (int j = 0; j < QPT4; j++)
                pbv[j] = *(const float4*)(br + (bq + 16 * j) * 4);
        }

#pragma unroll
        for (int ks = 0; ks < 2; ks++) {
            uint32_t BF[NF][2];
            uint32_t brow = (uint32_t)(ks * 16 + (lane & 15)) * BSTRIDE;
#pragma unroll
            for (int j = 0; j < NF / 2; j++) {
                uint32_t coff = (uint32_t)(wn * WN + j * 16 + ((lane >> 4) & 1) * 8) * 2;
                uint32_t r[4];
                ldsm4t(r, sB + brow + coff);
                BF[2*j][0] = r[0]; BF[2*j][1] = r[1];
                BF[2*j+1][0] = r[2]; BF[2*j+1][1] = r[3];
            }
            uint32_t acolB = (uint32_t)ks * 32 + ((lane >> 4) & 1) * 16;
            {
                uint32_t AF[2][4];
#pragma unroll
                for (int f = 0; f < 2; f++) {
                    uint32_t roff = (uint32_t)(wm * 32 + f * 16 + (lane & 15)) * 80 + acolB;
                    ldsm4(AF[f], sA_hi + roff);
                }
#pragma unroll
                for (int f = 0; f < 2; f++)
#pragma unroll
                    for (int g = 0; g < NF; g++)
                        mmaf16(acc[f][g], AF[f], BF[g]);
            }
            {
                uint32_t AF[2][4];
#pragma unroll
                for (int f = 0; f < 2; f++) {
                    uint32_t roff = (uint32_t)(wm * 32 + f * 16 + (lane & 15)) * 80 + acolB;
                    ldsm4(AF[f], sA_lo + roff);
                }
#pragma unroll
                for (int f = 0; f < 2; f++)
#pragma unroll
                    for (int g = 0; g < NF; g++)
                        mmaf16(acc[f][g], AF[f], BF[g]);
            }
        }
        __syncthreads();
    }

#pragma unroll
    for (int f = 0; f < 2; f++) {
#pragma unroll
        for (int g = 0; g < NF; g++) {
            int r0 = m0 + wm * 32 + f * 16 + (lane >> 2);
            int col = n0 + wn * WN + g * 8 + (lane & 3) * 2;
            float* p = Cout + (size_t)r0 * Nglob + col;
            *(float2*)p = make_float2(acc[f][g][0], acc[f][g][1]);
            *(float2*)(p + 8 * (size_t)Nglob) = make_float2(acc[f][g][2], acc[f][g][3]);
        }
    }
}

// ---------------- down GEMM: UV-shaped (BN=256, BK=32), split-K=4 ----------------
// partial[z][2048, 512] = (c3 . h)[:, z*4096:(z+1)*4096] @ Wd[z*4096:(z+1)*4096, :]
// Buffers: z=0 -> g_O, z=1 -> g_U, z=2 -> g_U + 1M floats, z=3 -> g_V (all dead scratch).
// Grid (2, 16, 4) = 128 blocks, 512 threads, 128 iters: identical per-iter shape to gemm7<256>.
__global__ void __launch_bounds__(512, 1) gemm9(const float* __restrict__ Bw)
{
    constexpr int BN = 256;
    constexpr int WN = 64;
    constexpr int NF = 8;
    constexpr int AMB = 128 * 80;
    constexpr int BSTRIDE = BN * 2 + 16;   // 528
    constexpr int BMB = 32 * BSTRIDE;
    constexpr int QPT4 = 4;
    constexpr int NG = 512;

    __shared__ __align__(128) char smem_raw[2 * AMB + BMB];  // 37376
    uint32_t sA_hi = smem_u32(smem_raw);
    uint32_t sA_lo = sA_hi + AMB;
    uint32_t sB    = sA_hi + 2 * AMB;

    float* part[4] = { g_O, g_U, g_U + (size_t)Mm * Dd, g_V };
    float* Cout = part[blockIdx.z];
    int kglob0 = blockIdx.z * 4096;

    int t = threadIdx.x, lane = t & 31, warp = t >> 5;
    int wm = warp & 3, wn = warp >> 2;
    int m0 = blockIdx.y * 128, n0 = blockIdx.x * BN;

    // A staging: 4 threads per row, 8 floats each (BK=32)
    int arow = t >> 2, aq = t & 3;
    const float* aRowBase = g_H + (size_t)(m0 + arow) * 1024 + aq * 8;
    const float* crow = g_c3 + ((m0 + arow) & 127) * 16;
    uint32_t aoff = (uint32_t)arow * 80 + aq * 16;

    // B staging: 16 threads per k-row (32 rows), 4 float4 each
    int krow = t >> 4;
    int bq = t & 15;
    const float* bRowBase = Bw + (size_t)(kglob0 + krow) * NG + n0;
    uint32_t bRowOff = (uint32_t)krow * BSTRIDE;

    float acc[2][NF][4];
#pragma unroll
    for (int f = 0; f < 2; f++)
#pragma unroll
        for (int g = 0; g < NF; g++)
#pragma unroll
            for (int j = 0; j < 4; j++) acc[f][g][j] = 0.f;

    const int nit = 128;   // 4096 / 32

    float4 pa0, pa1, pbv[QPT4];
    float psc;
    {
        int ktg = kglob0;
        psc = crow[ktg >> 10];
        const float* ar = aRowBase + (ktg & 1023);
        pa0 = *(const float4*)(ar + 0);
        pa1 = *(const float4*)(ar + 4);
#pragma unroll
        for (int j = 0; j < QPT4; j++)
            pbv[j] = *(const float4*)(bRowBase + (bq + 16 * j) * 4);
    }

    for (int it = 0; it < nit; it++) {
        cvtA_store8(pa0, pa1, psc, sA_hi + aoff, sA_lo + aoff);
#pragma unroll
        for (int j = 0; j < QPT4; j++)
            cvtB_store4(pbv[j], sB + bRowOff + (bq + 16 * j) * 8);
        __syncthreads();

        if (it + 1 < nit) {
            int ktn = (it + 1) << 5;
            int ktg = kglob0 + ktn;
            psc = crow[ktg >> 10];
            const float* ar = aRowBase + (ktg & 1023);
            pa0 = *(const float4*)(ar + 0);
            pa1 = *(const float4*)(ar + 4);
            const float* br = bRowBase + (size_t)ktn * NG;
#pragma unroll
            for (int j = 0; j < QPT4; j++)
                pbv[j] = *(const float4*)(br + (bq + 16 * j) * 4);
        }

#pragma unroll
        for (int ks = 0; ks < 2; ks++) {
            uint32_t BF[NF][2];
            uint32_t brow = (uint32_t)(ks * 16 + (lane & 15)) * BSTRIDE;
#pragma unroll
            for (int j = 0; j < NF / 2; j++) {
                uint32_t coff = (uint32_t)(wn * WN + j * 16 + ((lane >> 4) & 1) * 8) * 2;
                uint32_t r[4];
                ldsm4t(r, sB + brow + coff);
                BF[2*j][0] = r[0]; BF[2*j][1] = r[1];
                BF[2*j+1][0] = r[2]; BF[2*j+1][1] = r[3];
            }
            uint32_t acolB = (uint32_t)ks * 32 + ((lane >> 4) & 1) * 16;
            {
                uint32_t AF[2][4];
#pragma unroll
                for (int f = 0; f < 2; f++) {
                    uint32_t roff = (uint32_t)(wm * 32 + f * 16 + (lane & 15)) * 80 + acolB;
                    ldsm4(AF[f], sA_hi + roff);
                }
#pragma unroll
                for (int f = 0; f < 2; f++)
#pragma unroll
                    for (int g = 0; g < NF; g++)
                        mmaf16(acc[f][g], AF[f], BF[g]);
            }
            {
                uint32_t AF[2][4];
#pragma unroll
                for (int f = 0; f < 2; f++) {
                    uint32_t roff = (uint32_t)(wm * 32 + f * 16 + (lane & 15)) * 80 + acolB;
                    ldsm4(AF[f], sA_lo + roff);
                }
#pragma unroll
                for (int f = 0; f < 2; f++)
#pragma unroll
                    for (int g = 0; g < NF; g++)
                        mmaf16(acc[f][g], AF[f], BF[g]);
            }
        }
        __syncthreads();
    }

    // epilogue
#pragma unroll
    for (int f = 0; f < 2; f++) {
#pragma unroll
        for (int g = 0; g < NF; g++) {
            int r0 = m0 + wm * 32 + f * 16 + (lane >> 2);
            int col = n0 + wn * WN + g * 8 + (lane & 3) * 2;
            float* p = Cout + (size_t)r0 * NG + col;
            *(float2*)p = make_float2(acc[f][g][0], acc[f][g][1]);
            *(float2*)(p + 8 * NG) = make_float2(acc[f][g][2], acc[f][g][3]);
        }
    }
}

// ---------------- elementwise h ----------------
__global__ void h_kernel(const float* __restrict__ usp, const float* __restrict__ vsp) {
    const float SQRT_D = 22.62741699796952f;
    int i4 = blockIdx.x * blockDim.x + threadIdx.x;
    if (i4 >= Mm * Ff / 4) return;
    int m  = i4 >> 8;
    int f  = (i4 & 255) * 4;
    int l  = m & 127;

    float4 u  = *(const float4*)(g_U   + (size_t)m * Ff + f);
    float4 v  = *(const float4*)(g_V   + (size_t)m * Ff + f);
    float4 ig = *(const float4*)(g_ing + (size_t)l * Ff + f);
    float4 iu = *(const float4*)(g_inu + (size_t)l * Ff + f);
    float4 us = *(const float4*)(usp + f);
    float4 vs = *(const float4*)(vsp + f);

    float4 h;
    { float uu = u.x * ig.x, vv = v.x * iu.x; float zz = fabsf(vs.x) * SQRT_D * vv;
      h.x = (zz / (1.f + expf(-zz))) * (fabsf(us.x) * uu); }
    { float uu = u.y * ig.y, vv = v.y * iu.y; float zz = fabsf(vs.y) * SQRT_D * vv;
      h.y = (zz / (1.f + expf(-zz))) * (fabsf(us.y) * uu); }
    { float uu = u.z * ig.z, vv = v.z * iu.z; float zz = fabsf(vs.z) * SQRT_D * vv;
      h.z = (zz / (1.f + expf(-zz))) * (fabsf(us.z) * uu); }
    { float uu = u.w * ig.w, vv = v.w * iu.w; float zz = fabsf(vs.w) * SQRT_D * vv;
      h.w = (zz / (1.f + expf(-zz))) * (fabsf(us.w) * uu); }
    *(float4*)(g_H + (size_t)m * Ff + f) = h;
}

// ---------------- final: sum 4 split-K partials, apply down-norm, row L2 normalize ----------------
__global__ void out_kernel(float* __restrict__ out) {
    int m = blockIdx.x;
    int t = threadIdx.x;
    int l = m & 127;

    size_t off = (size_t)m * Dd + t * 4;
    float4 p0 = *(const float4*)(g_O + off);
    float4 p1 = *(const float4*)(g_U + off);
    float4 p2 = *(const float4*)(g_U + (size_t)Mm * Dd + off);
    float4 p3 = *(const float4*)(g_V + off);
    float4 iv = *(const float4*)(g_ind + (size_t)l * Dd + t * 4);

    float4 o;
    o.x = ((p0.x + p1.x) + (p2.x + p3.x)) * iv.x;
    o.y = ((p0.y + p1.y) + (p2.y + p3.y)) * iv.y;
    o.z = ((p0.z + p1.z) + (p2.z + p3.z)) * iv.z;
    o.w = ((p0.w + p1.w) + (p2.w + p3.w)) * iv.w;

    float ss = o.x*o.x + o.y*o.y + o.z*o.z + o.w*o.w;
#pragma unroll
    for (int offm = 16; offm > 0; offm >>= 1)
        ss += __shfl_xor_sync(0xffffffffu, ss, offm);

    __shared__ float ws[4];
    if ((t & 31) == 0) ws[t >> 5] = ss;
    __syncthreads();
    float tot = ws[0] + ws[1] + ws[2] + ws[3];
    float sc = 1.f / fmaxf(sqrtf(tot), 1e-12f);

    o.x *= sc; o.y *= sc; o.z *= sc; o.w *= sc;
    *(float4*)(out + off) = o;
}

// ---------------- launch ----------------
extern "C" void kernel_launch(void* const* d_in, const int* in_sizes, int n_in,
                              void* d_out, int out_size) {
    const float* x   = (const float*)d_in[0];
    const float* Wg  = (const float*)d_in[1];
    const float* Wu  = (const float*)d_in[2];
    const float* Wd  = (const float*)d_in[3];
    const float* t1  = (const float*)d_in[4];
    const float* t2  = (const float*)d_in[5];
    const float* t3  = (const float*)d_in[6];
    const float* usp = (const float*)d_in[7];
    const float* vsp = (const float*)d_in[8];
    float* out = (float*)d_out;

    softmax_kernel<<<3, 128>>>(t1, t2, t3);
    gram_kernel<<<dim3(32, 3), 256>>>(Wg, Wu, Wd);
    norm_kernel<<<dim3(8, 16, 3), 128>>>();

    // U and V fused (z=0 -> U, z=1 -> V): BN=256, 128 blocks, 512 threads
    gemm7<256><<<dim3(4, 16, 2), 512>>>(x, Wg, Wu, 0, 512, 9, 8192, 1024);
    // h = silu(vs*v) * (us*u)  (consumes g_U/g_V; they become scratch)
    h_kernel<<<2048, 256>>>(usp, vsp);
    // O partials: BN=256, split-K=4 -> g_O, g_U, g_U+1M, g_V
    gemm9<<<dim3(2, 16, 4), 512>>>(Wd);
    // final: sum 4 partials + normalize
    out_kernel<<<2048, 128>>>(out);
}

// round 14
// speedup vs baseline: 1.2113x; 1.0121x over previous
#include <cuda_runtime.h>
#include <cuda_fp16.h>
#include <math.h>
#include <stdint.h>

// Problem constants
#define Bb 16
#define Ll 128
#define Dd 512
#define Ff 1024
#define Mm 2048

// -------- device scratch (proven safe footprint) --------
__device__ __align__(16) float g_c1[Ll*16];
__device__ __align__(16) float g_c2[Ll*16];
__device__ __align__(16) float g_c3[Ll*16];
__device__ __align__(16) float g_Gg[256*Ff];
__device__ __align__(16) float g_Gu[256*Ff];
__device__ __align__(16) float g_Gd[256*Dd];
__device__ __align__(16) float g_ing[Ll*Ff];
__device__ __align__(16) float g_inu[Ll*Ff];
__device__ __align__(16) float g_ind[Ll*Dd];
__device__ __align__(16) float g_U[Mm*Ff];   // reused: split-K partials 1,2 for O
__device__ __align__(16) float g_V[Mm*Ff];   // reused: split-K partial 3 for O
__device__ __align__(16) float g_H[Mm*Ff];
__device__ __align__(16) float g_O[Mm*Dd];   // split-K partial 0

// ---------------- PTX helpers ----------------
__device__ __forceinline__ uint32_t smem_u32(const void* p) {
    uint32_t a;
    asm("{ .reg .u64 t; cvta.to.shared.u64 t, %1; cvt.u32.u64 %0, t; }" : "=r"(a) : "l"(p));
    return a;
}
__device__ __forceinline__ void ldsm4(uint32_t* r, uint32_t addr) {
    asm volatile("ldmatrix.sync.aligned.m8n8.x4.shared.b16 {%0,%1,%2,%3}, [%4];"
        : "=r"(r[0]), "=r"(r[1]), "=r"(r[2]), "=r"(r[3]) : "r"(addr));
}
__device__ __forceinline__ void ldsm4t(uint32_t* r, uint32_t addr) {
    asm volatile("ldmatrix.sync.aligned.m8n8.x4.trans.shared.b16 {%0,%1,%2,%3}, [%4];"
        : "=r"(r[0]), "=r"(r[1]), "=r"(r[2]), "=r"(r[3]) : "r"(addr));
}
__device__ __forceinline__ void mmaf16(float* c, const uint32_t* a, const uint32_t* b) {
    asm volatile("mma.sync.aligned.m16n8k16.row.col.f32.f16.f16.f32 "
        "{%0,%1,%2,%3}, {%4,%5,%6,%7}, {%8,%9}, {%0,%1,%2,%3};"
        : "+f"(c[0]), "+f"(c[1]), "+f"(c[2]), "+f"(c[3])
        : "r"(a[0]), "r"(a[1]), "r"(a[2]), "r"(a[3]), "r"(b[0]), "r"(b[1]));
}
__device__ __forceinline__ void sts16(uint32_t addr, uint4 v) {
    asm volatile("st.shared.v4.b32 [%0], {%1,%2,%3,%4};" ::
        "r"(addr), "r"(v.x), "r"(v.y), "r"(v.z), "r"(v.w) : "memory");
}
__device__ __forceinline__ void sts8(uint32_t addr, uint32_t x, uint32_t y) {
    asm volatile("st.shared.v2.b32 [%0], {%1,%2};" :: "r"(addr), "r"(x), "r"(y) : "memory");
}

// B: float4 -> 4 fp16 (8B), single matrix
__device__ __forceinline__ void cvtB_store4(float4 v, uint32_t addr) {
    __half2 h0 = __float22half2_rn(make_float2(v.x, v.y));
    __half2 h1 = __float22half2_rn(make_float2(v.z, v.w));
    sts8(addr, *(uint32_t*)&h0, *(uint32_t*)&h1);
}
// A: 8 scaled floats -> fp16 hi 16B + fp16 lo 16B
__device__ __forceinline__ void cvtA_store8(float4 va, float4 vb, float sc,
                                            uint32_t hiAddr, uint32_t loAddr) {
    va.x *= sc; va.y *= sc; va.z *= sc; va.w *= sc;
    vb.x *= sc; vb.y *= sc; vb.z *= sc; vb.w *= sc;
    __half2 h0 = __float22half2_rn(make_float2(va.x, va.y));
    __half2 h1 = __float22half2_rn(make_float2(va.z, va.w));
    __half2 h2 = __float22half2_rn(make_float2(vb.x, vb.y));
    __half2 h3 = __float22half2_rn(make_float2(vb.z, vb.w));
    float2 f0 = __half22float2(h0);
    float2 f1 = __half22float2(h1);
    float2 f2 = __half22float2(h2);
    float2 f3 = __half22float2(h3);
    __half2 l0 = __float22half2_rn(make_float2(va.x - f0.x, va.y - f0.y));
    __half2 l1 = __float22half2_rn(make_float2(va.z - f1.x, va.w - f1.y));
    __half2 l2 = __float22half2_rn(make_float2(vb.x - f2.x, vb.y - f2.y));
    __half2 l3 = __float22half2_rn(make_float2(vb.z - f3.x, vb.w - f3.y));
    sts16(hiAddr, make_uint4(*(uint32_t*)&h0, *(uint32_t*)&h1, *(uint32_t*)&h2, *(uint32_t*)&h3));
    sts16(loAddr, make_uint4(*(uint32_t*)&l0, *(uint32_t*)&l1, *(uint32_t*)&l2, *(uint32_t*)&l3));
}

// ---------------- softmax ----------------
__global__ void softmax_kernel(const float* __restrict__ t1,
                               const float* __restrict__ t2,
                               const float* __restrict__ t3) {
    const float* src = (blockIdx.x == 0) ? t1 : (blockIdx.x == 1) ? t2 : t3;
    float* dst = (blockIdx.x == 0) ? g_c1 : (blockIdx.x == 1) ? g_c2 : g_c3;
    int l = threadIdx.x;
    float v[16];
    float mx = -1e30f;
#pragma unroll
    for (int k = 0; k < 16; k++) { v[k] = src[l*16 + k]; mx = fmaxf(mx, v[k]); }
    float s = 0.f;
#pragma unroll
    for (int k = 0; k < 16; k++) { v[k] = expf(v[k] - mx); s += v[k]; }
    float inv = 1.f / s;
#pragma unroll
    for (int k = 0; k < 16; k++) dst[l*16 + k] = v[k] * inv;
}

// ---------------- Gram ----------------
__global__ void gram_kernel(const float* __restrict__ Wg,
                            const float* __restrict__ Wu,
                            const float* __restrict__ Wd) {
    int w = blockIdx.y;
    const float* W; float* G; int R, C;
    if (w == 0)      { W = Wg; G = g_Gg; R = Dd; C = Ff; }
    else if (w == 1) { W = Wu; G = g_Gu; R = Dd; C = Ff; }
    else             { W = Wd; G = g_Gd; R = Ff; C = Dd; }
    int c0 = blockIdx.x * 32;
    if (c0 >= C) return;

    __shared__ __align__(16) float s[16][8][32];
    int t = threadIdx.x;
    int cc = t & 31;
    int pg = t >> 5;
    float acc[32];
#pragma unroll
    for (int i = 0; i < 32; i++) acc[i] = 0.f;

    for (int r0 = 0; r0 < R; r0 += 8) {
        __syncthreads();
#pragma unroll
        for (int j = 0; j < 16; j++) {
            int idx = j * 256 + t;
            int lc = idx & 31, rr = (idx >> 5) & 7, k = idx >> 8;
            s[k][rr][lc] = W[(size_t)k * R * C + (size_t)(r0 + rr) * C + c0 + lc];
        }
        __syncthreads();
#pragma unroll
        for (int rr = 0; rr < 8; rr++) {
            float wv[16];
#pragma unroll
            for (int k = 0; k < 16; k++) wv[k] = s[k][rr][cc];
            float a0 = s[(pg << 1) + 0][rr][cc];
            float a1 = s[(pg << 1) + 1][rr][cc];
#pragma unroll
            for (int pp = 0; pp < 16; pp++) acc[pp]      += a0 * wv[pp];
#pragma unroll
            for (int pp = 0; pp < 16; pp++) acc[16 + pp] += a1 * wv[pp];
        }
    }
#pragma unroll
    for (int pp = 0; pp < 32; pp++) {
        int p = ((pg << 1) + (pp >> 4)) * 16 + (pp & 15);
        G[(size_t)p * C + c0 + cc] = acc[pp];
    }
}

// ---------------- inverse norms: 8 tokens per block ----------------
__global__ void norm_kernel() {
    int w = blockIdx.z;
    int l0 = blockIdx.y * 8;
    const float* G; const float* coef; float* out; int C;
    if (w == 0)      { G = g_Gg; coef = g_c1; out = g_ing; C = Ff; }
    else if (w == 1) { G = g_Gu; coef = g_c2; out = g_inu; C = Ff; }
    else             { G = g_Gd; coef = g_c3; out = g_ind; C = Dd; }
    int c = blockIdx.x * 128 + threadIdx.x;
    if (c >= C) return;   // guard: down plane has C=512

    __shared__ float w2[8][256];
#pragma unroll
    for (int i = 0; i < 16; i++) {
        int idx = threadIdx.x * 16 + i;
        int li = idx >> 8, p = idx & 255;
        w2[li][p] = coef[(l0 + li) * 16 + (p >> 4)] * coef[(l0 + li) * 16 + (p & 15)];
    }
    __syncthreads();

    float acc[8];
#pragma unroll
    for (int i = 0; i < 8; i++) acc[i] = 0.f;
#pragma unroll 4
    for (int p = 0; p < 256; p++) {
        float g = G[(size_t)p * C + c];
#pragma unroll
        for (int i = 0; i < 8; i++) acc[i] += w2[i][p] * g;
    }
#pragma unroll
    for (int i = 0; i < 8; i++)
        out[(l0 + i) * C + c] = 1.f / fmaxf(sqrtf(fmaxf(acc[i], 0.f)), 1e-12f);
}

// ---------------- UV GEMM: fp16 2-MMA, 512 thr, reg prefetch, DOUBLE-BUFFERED smem ----------------
// One __syncthreads per iteration; STS of next tile overlaps MMA of current tile.
__global__ void __launch_bounds__(512, 1) gemm11(
    const float* __restrict__ A0,
    const float* __restrict__ Bw0, const float* __restrict__ Bw1,
    int Ka, int ksegShift, int Ktot, int Nglob)
{
    constexpr int BN = 256;
    constexpr int WN = 64;
    constexpr int NF = 8;
    constexpr int AMB = 128 * 80;
    constexpr int BSTRIDE = BN * 2 + 16;   // 528
    constexpr int BMB = 32 * BSTRIDE;
    constexpr int STG = 2 * AMB + BMB;     // 37376
    constexpr int QPT4 = 4;

    extern __shared__ __align__(128) char dynsmem[];
    uint32_t base = smem_u32(dynsmem);

    const float* coef; float* Cout; const float* Bw;
    const float* Ap = A0;
    if (blockIdx.z == 0) { coef = g_c1; Bw = Bw0; Cout = g_U; }
    else                 { coef = g_c2; Bw = Bw1; Cout = g_V; }

    int t = threadIdx.x, lane = t & 31, warp = t >> 5;
    int wm = warp & 3, wn = warp >> 2;
    int m0 = blockIdx.y * 128, n0 = blockIdx.x * BN;

    int arow = t >> 2, aq = t & 3;
    const float* aRow = Ap + (size_t)(m0 + arow) * Ka + aq * 8;
    const float* crow = coef + ((m0 + arow) & 127) * 16;
    uint32_t aoff = (uint32_t)arow * 80 + aq * 16;

    int krow = t >> 4;
    int bq = t & 15;
    const float* bRowBase = Bw + (size_t)krow * Nglob + n0;
    uint32_t bRowOff = (uint32_t)krow * BSTRIDE;

    float acc[2][NF][4];
#pragma unroll
    for (int f = 0; f < 2; f++)
#pragma unroll
        for (int g = 0; g < NF; g++)
#pragma unroll
            for (int j = 0; j < 4; j++) acc[f][g][j] = 0.f;

    int nit = Ktot >> 5;

    float4 pa0, pa1, pbv[QPT4];
    float psc;
    // prologue: load + store iter 0 into stage 0
    {
        psc = crow[0];
        pa0 = *(const float4*)(aRow + 0);
        pa1 = *(const float4*)(aRow + 4);
#pragma unroll
        for (int j = 0; j < QPT4; j++)
            pbv[j] = *(const float4*)(bRowBase + (bq + 16 * j) * 4);
        cvtA_store8(pa0, pa1, psc, base + aoff, base + AMB + aoff);
#pragma unroll
        for (int j = 0; j < QPT4; j++)
            cvtB_store4(pbv[j], base + 2 * AMB + bRowOff + (bq + 16 * j) * 8);
    }
    __syncthreads();

    for (int it = 0; it < nit; it++) {
        uint32_t cur = base + (uint32_t)(it & 1) * STG;
        uint32_t nxt = base + (uint32_t)((it + 1) & 1) * STG;
        bool more = (it + 1 < nit);

        // LDG next tile into regs (lands during MMA)
        if (more) {
            int ktn = (it + 1) << 5;
            psc = crow[ktn >> ksegShift];
            const float* ar = aRow + (ktn & (Ka - 1));
            pa0 = *(const float4*)(ar + 0);
            pa1 = *(const float4*)(ar + 4);
            const float* br = bRowBase + (size_t)ktn * Nglob;
#pragma unroll
            for (int j = 0; j < QPT4; j++)
                pbv[j] = *(const float4*)(br + (bq + 16 * j) * 4);
        }

        // ---- MMA on cur ----
        uint32_t sA_hi = cur, sA_lo = cur + AMB, sB = cur + 2 * AMB;
#pragma unroll
        for (int ks = 0; ks < 2; ks++) {
            uint32_t BF[NF][2];
            uint32_t brow = (uint32_t)(ks * 16 + (lane & 15)) * BSTRIDE;
#pragma unroll
            for (int j = 0; j < NF / 2; j++) {
                uint32_t coff = (uint32_t)(wn * WN + j * 16 + ((lane >> 4) & 1) * 8) * 2;
                uint32_t r[4];
                ldsm4t(r, sB + brow + coff);
                BF[2*j][0] = r[0]; BF[2*j][1] = r[1];
                BF[2*j+1][0] = r[2]; BF[2*j+1][1] = r[3];
            }
            uint32_t acolB = (uint32_t)ks * 32 + ((lane >> 4) & 1) * 16;
            {
                uint32_t AF[2][4];
#pragma unroll
                for (int f = 0; f < 2; f++) {
                    uint32_t roff = (uint32_t)(wm * 32 + f * 16 + (lane & 15)) * 80 + acolB;
                    ldsm4(AF[f], sA_hi + roff);
                }
#pragma unroll
                for (int f = 0; f < 2; f++)
#pragma unroll
                    for (int g = 0; g < NF; g++)
                        mmaf16(acc[f][g], AF[f], BF[g]);
            }
            {
                uint32_t AF[2][4];
#pragma unroll
                for (int f = 0; f < 2; f++) {
                    uint32_t roff = (uint32_t)(wm * 32 + f * 16 + (lane & 15)) * 80 + acolB;
                    ldsm4(AF[f], sA_lo + roff);
                }
#pragma unroll
                for (int f = 0; f < 2; f++)
#pragma unroll
                    for (int g = 0; g < NF; g++)
                        mmaf16(acc[f][g], AF[f], BF[g]);
            }
        }

        // ---- store next tile into other stage (overlaps MMA across warps) ----
        if (more) {
            cvtA_store8(pa0, pa1, psc, nxt + aoff, nxt + AMB + aoff);
#pragma unroll
            for (int j = 0; j < QPT4; j++)
                cvtB_store4(pbv[j], nxt + 2 * AMB + bRowOff + (bq + 16 * j) * 8);
        }
        __syncthreads();
    }

#pragma unroll
    for (int f = 0; f < 2; f++) {
#pragma unroll
        for (int g = 0; g < NF; g++) {
            int r0 = m0 + wm * 32 + f * 16 + (lane >> 2);
            int col = n0 + wn * WN + g * 8 + (lane & 3) * 2;
            float* p = Cout + (size_t)r0 * Nglob + col;
            *(float2*)p = make_float2(acc[f][g][0], acc[f][g][1]);
            *(float2*)(p + 8 * (size_t)Nglob) = make_float2(acc[f][g][2], acc[f][g][3]);
        }
    }
}

// ---------------- down GEMM: UV-shaped, split-K=4, DOUBLE-BUFFERED ----------------
__global__ void __launch_bounds__(512, 1) gemm12(const float* __restrict__ Bw)
{
    constexpr int BN = 256;
    constexpr int WN = 64;
    constexpr int NF = 8;
    constexpr int AMB = 128 * 80;
    constexpr int BSTRIDE = BN * 2 + 16;   // 528
    constexpr int BMB = 32 * BSTRIDE;
    constexpr int STG = 2 * AMB + BMB;     // 37376
    constexpr int QPT4 = 4;
    constexpr int NG = 512;

    extern __shared__ __align__(128) char dynsmem[];
    uint32_t base = smem_u32(dynsmem);

    float* part[4] = { g_O, g_U, g_U + (size_t)Mm * Dd, g_V };
    float* Cout = part[blockIdx.z];
    int kglob0 = blockIdx.z * 4096;

    int t = threadIdx.x, lane = t & 31, warp = t >> 5;
    int wm = warp & 3, wn = warp >> 2;
    int m0 = blockIdx.y * 128, n0 = blockIdx.x * BN;

    int arow = t >> 2, aq = t & 3;
    const float* aRowBase = g_H + (size_t)(m0 + arow) * 1024 + aq * 8;
    const float* crow = g_c3 + ((m0 + arow) & 127) * 16;
    uint32_t aoff = (uint32_t)arow * 80 + aq * 16;

    int krow = t >> 4;
    int bq = t & 15;
    const float* bRowBase = Bw + (size_t)(kglob0 + krow) * NG + n0;
    uint32_t bRowOff = (uint32_t)krow * BSTRIDE;

    float acc[2][NF][4];
#pragma unroll
    for (int f = 0; f < 2; f++)
#pragma unroll
        for (int g = 0; g < NF; g++)
#pragma unroll
            for (int j = 0; j < 4; j++) acc[f][g][j] = 0.f;

    const int nit = 128;

    float4 pa0, pa1, pbv[QPT4];
    float psc;
    {
        int ktg = kglob0;
        psc = crow[ktg >> 10];
        const float* ar = aRowBase + (ktg & 1023);
        pa0 = *(const float4*)(ar + 0);
        pa1 = *(const float4*)(ar + 4);
#pragma unroll
        for (int j = 0; j < QPT4; j++)
            pbv[j] = *(const float4*)(bRowBase + (bq + 16 * j) * 4);
        cvtA_store8(pa0, pa1, psc, base + aoff, base + AMB + aoff);
#pragma unroll
        for (int j = 0; j < QPT4; j++)
            cvtB_store4(pbv[j], base + 2 * AMB + bRowOff + (bq + 16 * j) * 8);
    }
    __syncthreads();

    for (int it = 0; it < nit; it++) {
        uint32_t cur = base + (uint32_t)(it & 1) * STG;
        uint32_t nxt = base + (uint32_t)((it + 1) & 1) * STG;
        bool more = (it + 1 < nit);

        if (more) {
            int ktn = (it + 1) << 5;
            int ktg = kglob0 + ktn;
            psc = crow[ktg >> 10];
            const float* ar = aRowBase + (ktg & 1023);
            pa0 = *(const float4*)(ar + 0);
            pa1 = *(const float4*)(ar + 4);
            const float* br = bRowBase + (size_t)ktn * NG;
#pragma unroll
            for (int j = 0; j < QPT4; j++)
                pbv[j] = *(const float4*)(br + (bq + 16 * j) * 4);
        }

        uint32_t sA_hi = cur, sA_lo = cur + AMB, sB = cur + 2 * AMB;
#pragma unroll
        for (int ks = 0; ks < 2; ks++) {
            uint32_t BF[NF][2];
            uint32_t brow = (uint32_t)(ks * 16 + (lane & 15)) * BSTRIDE;
#pragma unroll
            for (int j = 0; j < NF / 2; j++) {
                uint32_t coff = (uint32_t)(wn * WN + j * 16 + ((lane >> 4) & 1) * 8) * 2;
                uint32_t r[4];
                ldsm4t(r, sB + brow + coff);
                BF[2*j][0] = r[0]; BF[2*j][1] = r[1];
                BF[2*j+1][0] = r[2]; BF[2*j+1][1] = r[3];
            }
            uint32_t acolB = (uint32_t)ks * 32 + ((lane >> 4) & 1) * 16;
            {
                uint32_t AF[2][4];
#pragma unroll
                for (int f = 0; f < 2; f++) {
                    uint32_t roff = (uint32_t)(wm * 32 + f * 16 + (lane & 15)) * 80 + acolB;
                    ldsm4(AF[f], sA_hi + roff);
                }
#pragma unroll
                for (int f = 0; f < 2; f++)
#pragma unroll
                    for (int g = 0; g < NF; g++)
                        mmaf16(acc[f][g], AF[f], BF[g]);
            }
            {
                uint32_t AF[2][4];
#pragma unroll
                for (int f = 0; f < 2; f++) {
                    uint32_t roff = (uint32_t)(wm * 32 + f * 16 + (lane & 15)) * 80 + acolB;
                    ldsm4(AF[f], sA_lo + roff);
                }
#pragma unroll
                for (int f = 0; f < 2; f++)
#pragma unroll
                    for (int g = 0; g < NF; g++)
                        mmaf16(acc[f][g], AF[f], BF[g]);
            }
        }

        if (more) {
            cvtA_store8(pa0, pa1, psc, nxt + aoff, nxt + AMB + aoff);
#pragma unroll
            for (int j = 0; j < QPT4; j++)
                cvtB_store4(pbv[j], nxt + 2 * AMB + bRowOff + (bq + 16 * j) * 8);
        }
        __syncthreads();
    }

#pragma unroll
    for (int f = 0; f < 2; f++) {
#pragma unroll
        for (int g = 0; g < NF; g++) {
            int r0 = m0 + wm * 32 + f * 16 + (lane >> 2);
            int col = n0 + wn * WN + g * 8 + (lane & 3) * 2;
            float* p = Cout + (size_t)r0 * NG + col;
            *(float2*)p = make_float2(acc[f][g][0], acc[f][g][1]);
            *(float2*)(p + 8 * NG) = make_float2(acc[f][g][2], acc[f][g][3]);
        }
    }
}

// ---------------- elementwise h ----------------
__global__ void h_kernel(const float* __restrict__ usp, const float* __restrict__ vsp) {
    const float SQRT_D = 22.62741699796952f;
    int i4 = blockIdx.x * blockDim.x + threadIdx.x;
    if (i4 >= Mm * Ff / 4) return;
    int m  = i4 >> 8;
    int f  = (i4 & 255) * 4;
    int l  = m & 127;

    float4 u  = *(const float4*)(g_U   + (size_t)m * Ff + f);
    float4 v  = *(const float4*)(g_V   + (size_t)m * Ff + f);
    float4 ig = *(const float4*)(g_ing + (size_t)l * Ff + f);
    float4 iu = *(const float4*)(g_inu + (size_t)l * Ff + f);
    float4 us = *(const float4*)(usp + f);
    float4 vs = *(const float4*)(vsp + f);

    float4 h;
    { float uu = u.x * ig.x, vv = v.x * iu.x; float zz = fabsf(vs.x) * SQRT_D * vv;
      h.x = (zz / (1.f + expf(-zz))) * (fabsf(us.x) * uu); }
    { float uu = u.y * ig.y, vv = v.y * iu.y; float zz = fabsf(vs.y) * SQRT_D * vv;
      h.y = (zz / (1.f + expf(-zz))) * (fabsf(us.y) * uu); }
    { float uu = u.z * ig.z, vv = v.z * iu.z; float zz = fabsf(vs.z) * SQRT_D * vv;
      h.z = (zz / (1.f + expf(-zz))) * (fabsf(us.z) * uu); }
    { float uu = u.w * ig.w, vv = v.w * iu.w; float zz = fabsf(vs.w) * SQRT_D * vv;
      h.w = (zz / (1.f + expf(-zz))) * (fabsf(us.w) * uu); }
    *(float4*)(g_H + (size_t)m * Ff + f) = h;
}

// ---------------- final: sum 4 split-K partials, apply down-norm, row L2 normalize ----------------
__global__ void out_kernel(float* __restrict__ out) {
    int m = blockIdx.x;
    int t = threadIdx.x;
    int l = m & 127;

    size_t off = (size_t)m * Dd + t * 4;
    float4 p0 = *(const float4*)(g_O + off);
    float4 p1 = *(const float4*)(g_U + off);
    float4 p2 = *(const float4*)(g_U + (size_t)Mm * Dd + off);
    float4 p3 = *(const float4*)(g_V + off);
    float4 iv = *(const float4*)(g_ind + (size_t)l * Dd + t * 4);

    float4 o;
    o.x = ((p0.x + p1.x) + (p2.x + p3.x)) * iv.x;
    o.y = ((p0.y + p1.y) + (p2.y + p3.y)) * iv.y;
    o.z = ((p0.z + p1.z) + (p2.z + p3.z)) * iv.z;
    o.w = ((p0.w + p1.w) + (p2.w + p3.w)) * iv.w;

    float ss = o.x*o.x + o.y*o.y + o.z*o.z + o.w*o.w;
#pragma unroll
    for (int offm = 16; offm > 0; offm >>= 1)
        ss += __shfl_xor_sync(0xffffffffu, ss, offm);

    __shared__ float ws[4];
    if ((t & 31) == 0) ws[t >> 5] = ss;
    __syncthreads();
    float tot = ws[0] + ws[1] + ws[2] + ws[3];
    float sc = 1.f / fmaxf(sqrtf(tot), 1e-12f);

    o.x *= sc; o.y *= sc; o.z *= sc; o.w *= sc;
    *(float4*)(out + off) = o;
}

// ---------------- launch ----------------
extern "C" void kernel_launch(void* const* d_in, const int* in_sizes, int n_in,
                              void* d_out, int out_size) {
    const float* x   = (const float*)d_in[0];
    const float* Wg  = (const float*)d_in[1];
    const float* Wu  = (const float*)d_in[2];
    const float* Wd  = (const float*)d_in[3];
    const float* t1  = (const float*)d_in[4];
    const float* t2  = (const float*)d_in[5];
    const float* t3  = (const float*)d_in[6];
    const float* usp = (const float*)d_in[7];
    const float* vsp = (const float*)d_in[8];
    float* out = (float*)d_out;

    const int DSMEM = 2 * (2 * 128 * 80 + 32 * 528);   // 74752
    cudaFuncSetAttribute(gemm11, cudaFuncAttributeMaxDynamicSharedMemorySize, DSMEM);
    cudaFuncSetAttribute(gemm12, cudaFuncAttributeMaxDynamicSharedMemorySize, DSMEM);

    softmax_kernel<<<3, 128>>>(t1, t2, t3);
    gram_kernel<<<dim3(32, 3), 256>>>(Wg, Wu, Wd);
    norm_kernel<<<dim3(8, 16, 3), 128>>>();

    // U and V fused (z=0 -> U, z=1 -> V): BN=256, 128 blocks, 512 threads, double-buffered
    gemm11<<<dim3(4, 16, 2), 512, DSMEM>>>(x, Wg, Wu, 512, 9, 8192, 1024);
    // h = silu(vs*v) * (us*u)  (consumes g_U/g_V; they become scratch)
    h_kernel<<<2048, 256>>>(usp, vsp);
    // O partials: BN=256, split-K=4 -> g_O, g_U, g_U+1M, g_V, double-buffered
    gemm12<<<dim3(2, 16, 4), 512, DSMEM>>>(Wd);
    // final: sum 4 partials + normalize
    out_kernel<<<2048, 128>>>(out);
}

// round 15
// speedup vs baseline: 1.5783x; 1.3031x over previous
#include <cuda_runtime.h>
#include <cuda_fp16.h>
#include <math.h>
#include <stdint.h>

// Problem constants
#define Bb 16
#define Ll 128
#define Dd 512
#define Ff 1024
#define Mm 2048

// -------- device scratch (proven safe footprint) --------
__device__ __align__(16) float g_c1[Ll*16];
__device__ __align__(16) float g_c2[Ll*16];
__device__ __align__(16) float g_c3[Ll*16];
__device__ __align__(16) float g_Gg[256*Ff];
__device__ __align__(16) float g_Gu[256*Ff];
__device__ __align__(16) float g_Gd[256*Dd];
__device__ __align__(16) float g_ing[Ll*Ff];
__device__ __align__(16) float g_inu[Ll*Ff];
__device__ __align__(16) float g_ind[Ll*Dd];
__device__ __align__(16) float g_U[Mm*Ff];   // reused: split-K partials 1,2 for O
__device__ __align__(16) float g_V[Mm*Ff];   // reused: split-K partial 3 for O
__device__ __align__(16) float g_H[Mm*Ff];
__device__ __align__(16) float g_O[Mm*Dd];   // split-K partial 0

// ---------------- PTX helpers ----------------
__device__ __forceinline__ uint32_t smem_u32(const void* p) {
    uint32_t a;
    asm("{ .reg .u64 t; cvta.to.shared.u64 t, %1; cvt.u32.u64 %0, t; }" : "=r"(a) : "l"(p));
    return a;
}
__device__ __forceinline__ void ldsm4(uint32_t* r, uint32_t addr) {
    asm volatile("ldmatrix.sync.aligned.m8n8.x4.shared.b16 {%0,%1,%2,%3}, [%4];"
        : "=r"(r[0]), "=r"(r[1]), "=r"(r[2]), "=r"(r[3]) : "r"(addr));
}
__device__ __forceinline__ void ldsm4t(uint32_t* r, uint32_t addr) {
    asm volatile("ldmatrix.sync.aligned.m8n8.x4.trans.shared.b16 {%0,%1,%2,%3}, [%4];"
        : "=r"(r[0]), "=r"(r[1]), "=r"(r[2]), "=r"(r[3]) : "r"(addr));
}
__device__ __forceinline__ void mmaf16(float* c, const uint32_t* a, const uint32_t* b) {
    asm volatile("mma.sync.aligned.m16n8k16.row.col.f32.f16.f16.f32 "
        "{%0,%1,%2,%3}, {%4,%5,%6,%7}, {%8,%9}, {%0,%1,%2,%3};"
        : "+f"(c[0]), "+f"(c[1]), "+f"(c[2]), "+f"(c[3])
        : "r"(a[0]), "r"(a[1]), "r"(a[2]), "r"(a[3]), "r"(b[0]), "r"(b[1]));
}
__device__ __forceinline__ void sts16(uint32_t addr, uint4 v) {
    asm volatile("st.shared.v4.b32 [%0], {%1,%2,%3,%4};" ::
        "r"(addr), "r"(v.x), "r"(v.y), "r"(v.z), "r"(v.w) : "memory");
}
__device__ __forceinline__ void sts8(uint32_t addr, uint32_t x, uint32_t y) {
    asm volatile("st.shared.v2.b32 [%0], {%1,%2};" :: "r"(addr), "r"(x), "r"(y) : "memory");
}

// float4 -> 4 fp16 (8B)
__device__ __forceinline__ void cvt_store4(float4 v, uint32_t addr) {
    __half2 h0 = __float22half2_rn(make_float2(v.x, v.y));
    __half2 h1 = __float22half2_rn(make_float2(v.z, v.w));
    sts8(addr, *(uint32_t*)&h0, *(uint32_t*)&h1);
}
// 8 scaled floats -> 8 fp16 (16B)
__device__ __forceinline__ void cvt_store8s(float4 va, float4 vb, float sc, uint32_t addr) {
    va.x *= sc; va.y *= sc; va.z *= sc; va.w *= sc;
    vb.x *= sc; vb.y *= sc; vb.z *= sc; vb.w *= sc;
    __half2 h0 = __float22half2_rn(make_float2(va.x, va.y));
    __half2 h1 = __float22half2_rn(make_float2(va.z, va.w));
    __half2 h2 = __float22half2_rn(make_float2(vb.x, vb.y));
    __half2 h3 = __float22half2_rn(make_float2(vb.z, vb.w));
    sts16(addr, make_uint4(*(uint32_t*)&h0, *(uint32_t*)&h1, *(uint32_t*)&h2, *(uint32_t*)&h3));
}

// ---------------- softmax ----------------
__global__ void softmax_kernel(const float* __restrict__ t1,
                               const float* __restrict__ t2,
                               const float* __restrict__ t3) {
    const float* src = (blockIdx.x == 0) ? t1 : (blockIdx.x == 1) ? t2 : t3;
    float* dst = (blockIdx.x == 0) ? g_c1 : (blockIdx.x == 1) ? g_c2 : g_c3;
    int l = threadIdx.x;
    float v[16];
    float mx = -1e30f;
#pragma unroll
    for (int k = 0; k < 16; k++) { v[k] = src[l*16 + k]; mx = fmaxf(mx, v[k]); }
    float s = 0.f;
#pragma unroll
    for (int k = 0; k < 16; k++) { v[k] = expf(v[k] - mx); s += v[k]; }
    float inv = 1.f / s;
#pragma unroll
    for (int k = 0; k < 16; k++) dst[l*16 + k] = v[k] * inv;
}

// ---------------- Gram ----------------
__global__ void gram_kernel(const float* __restrict__ Wg,
                            const float* __restrict__ Wu,
                            const float* __restrict__ Wd) {
    int w = blockIdx.y;
    const float* W; float* G; int R, C;
    if (w == 0)      { W = Wg; G = g_Gg; R = Dd; C = Ff; }
    else if (w == 1) { W = Wu; G = g_Gu; R = Dd; C = Ff; }
    else             { W = Wd; G = g_Gd; R = Ff; C = Dd; }
    int c0 = blockIdx.x * 32;
    if (c0 >= C) return;

    __shared__ __align__(16) float s[16][8][32];
    int t = threadIdx.x;
    int cc = t & 31;
    int pg = t >> 5;
    float acc[32];
#pragma unroll
    for (int i = 0; i < 32; i++) acc[i] = 0.f;

    for (int r0 = 0; r0 < R; r0 += 8) {
        __syncthreads();
#pragma unroll
        for (int j = 0; j < 16; j++) {
            int idx = j * 256 + t;
            int lc = idx & 31, rr = (idx >> 5) & 7, k = idx >> 8;
            s[k][rr][lc] = W[(size_t)k * R * C + (size_t)(r0 + rr) * C + c0 + lc];
        }
        __syncthreads();
#pragma unroll
        for (int rr = 0; rr < 8; rr++) {
            float wv[16];
#pragma unroll
            for (int k = 0; k < 16; k++) wv[k] = s[k][rr][cc];
            float a0 = s[(pg << 1) + 0][rr][cc];
            float a1 = s[(pg << 1) + 1][rr][cc];
#pragma unroll
            for (int pp = 0; pp < 16; pp++) acc[pp]      += a0 * wv[pp];
#pragma unroll
            for (int pp = 0; pp < 16; pp++) acc[16 + pp] += a1 * wv[pp];
        }
    }
#pragma unroll
    for (int pp = 0; pp < 32; pp++) {
        int p = ((pg << 1) + (pp >> 4)) * 16 + (pp & 15);
        G[(size_t)p * C + c0 + cc] = acc[pp];
    }
}

// ---------------- inverse norms: 8 tokens per block ----------------
__global__ void norm_kernel() {
    int w = blockIdx.z;
    int l0 = blockIdx.y * 8;
    const float* G; const float* coef; float* out; int C;
    if (w == 0)      { G = g_Gg; coef = g_c1; out = g_ing; C = Ff; }
    else if (w == 1) { G = g_Gu; coef = g_c2; out = g_inu; C = Ff; }
    else             { G = g_Gd; coef = g_c3; out = g_ind; C = Dd; }
    int c = blockIdx.x * 128 + threadIdx.x;
    if (c >= C) return;   // guard: down plane has C=512

    __shared__ float w2[8][256];
#pragma unroll
    for (int i = 0; i < 16; i++) {
        int idx = threadIdx.x * 16 + i;
        int li = idx >> 8, p = idx & 255;
        w2[li][p] = coef[(l0 + li) * 16 + (p >> 4)] * coef[(l0 + li) * 16 + (p & 15)];
    }
    __syncthreads();

    float acc[8];
#pragma unroll
    for (int i = 0; i < 8; i++) acc[i] = 0.f;
#pragma unroll 4
    for (int p = 0; p < 256; p++) {
        float g = G[(size_t)p * C + c];
#pragma unroll
        for (int i = 0; i < 8; i++) acc[i] += w2[i][p] * g;
    }
#pragma unroll
    for (int i = 0; i < 8; i++)
        out[(l0 + i) * C + c] = 1.f / fmaxf(sqrtf(fmaxf(acc[i], 0.f)), 1e-12f);
}

// ---------------- UV GEMM: single fp16 A x fp16 B, 1 MMA, double-buffered ----------------
__global__ void __launch_bounds__(512, 1) gemm11(
    const float* __restrict__ A0,
    const float* __restrict__ Bw0, const float* __restrict__ Bw1,
    int Ka, int ksegShift, int Ktot, int Nglob)
{
    constexpr int BN = 256;
    constexpr int WN = 64;
    constexpr int NF = 8;
    constexpr int AMB = 128 * 80;          // single A matrix (32 fp16 + pad)
    constexpr int BSTRIDE = BN * 2 + 16;   // 528
    constexpr int BMB = 32 * BSTRIDE;
    constexpr int STG = AMB + BMB;         // 27136
    constexpr int QPT4 = 4;

    extern __shared__ __align__(128) char dynsmem[];
    uint32_t base = smem_u32(dynsmem);

    const float* coef; float* Cout; const float* Bw;
    const float* Ap = A0;
    if (blockIdx.z == 0) { coef = g_c1; Bw = Bw0; Cout = g_U; }
    else                 { coef = g_c2; Bw = Bw1; Cout = g_V; }

    int t = threadIdx.x, lane = t & 31, warp = t >> 5;
    int wm = warp & 3, wn = warp >> 2;
    int m0 = blockIdx.y * 128, n0 = blockIdx.x * BN;

    int arow = t >> 2, aq = t & 3;
    const float* aRow = Ap + (size_t)(m0 + arow) * Ka + aq * 8;
    const float* crow = coef + ((m0 + arow) & 127) * 16;
    uint32_t aoff = (uint32_t)arow * 80 + aq * 16;

    int krow = t >> 4;
    int bq = t & 15;
    const float* bRowBase = Bw + (size_t)krow * Nglob + n0;
    uint32_t bRowOff = (uint32_t)krow * BSTRIDE;

    float acc[2][NF][4];
#pragma unroll
    for (int f = 0; f < 2; f++)
#pragma unroll
        for (int g = 0; g < NF; g++)
#pragma unroll
            for (int j = 0; j < 4; j++) acc[f][g][j] = 0.f;

    int nit = Ktot >> 5;

    float4 pa0, pa1, pbv[QPT4];
    float psc;
    // prologue
    {
        psc = crow[0];
        pa0 = *(const float4*)(aRow + 0);
        pa1 = *(const float4*)(aRow + 4);
#pragma unroll
        for (int j = 0; j < QPT4; j++)
            pbv[j] = *(const float4*)(bRowBase + (bq + 16 * j) * 4);
        cvt_store8s(pa0, pa1, psc, base + aoff);
#pragma unroll
        for (int j = 0; j < QPT4; j++)
            cvt_store4(pbv[j], base + AMB + bRowOff + (bq + 16 * j) * 8);
    }
    __syncthreads();

    for (int it = 0; it < nit; it++) {
        uint32_t cur = base + (uint32_t)(it & 1) * STG;
        uint32_t nxt = base + (uint32_t)((it + 1) & 1) * STG;
        bool more = (it + 1 < nit);

        if (more) {
            int ktn = (it + 1) << 5;
            psc = crow[ktn >> ksegShift];
            const float* ar = aRow + (ktn & (Ka - 1));
            pa0 = *(const float4*)(ar + 0);
            pa1 = *(const float4*)(ar + 4);
            const float* br = bRowBase + (size_t)ktn * Nglob;
#pragma unroll
            for (int j = 0; j < QPT4; j++)
                pbv[j] = *(const float4*)(br + (bq + 16 * j) * 4);
        }

        uint32_t sA = cur, sB = cur + AMB;
#pragma unroll
        for (int ks = 0; ks < 2; ks++) {
            uint32_t BF[NF][2];
            uint32_t brow = (uint32_t)(ks * 16 + (lane & 15)) * BSTRIDE;
#pragma unroll
            for (int j = 0; j < NF / 2; j++) {
                uint32_t coff = (uint32_t)(wn * WN + j * 16 + ((lane >> 4) & 1) * 8) * 2;
                uint32_t r[4];
                ldsm4t(r, sB + brow + coff);
                BF[2*j][0] = r[0]; BF[2*j][1] = r[1];
                BF[2*j+1][0] = r[2]; BF[2*j+1][1] = r[3];
            }
            uint32_t acolB = (uint32_t)ks * 32 + ((lane >> 4) & 1) * 16;
            uint32_t AF[2][4];
#pragma unroll
            for (int f = 0; f < 2; f++) {
                uint32_t roff = (uint32_t)(wm * 32 + f * 16 + (lane & 15)) * 80 + acolB;
                ldsm4(AF[f], sA + roff);
            }
#pragma unroll
            for (int f = 0; f < 2; f++)
#pragma unroll
                for (int g = 0; g < NF; g++)
                    mmaf16(acc[f][g], AF[f], BF[g]);
        }

        if (more) {
            cvt_store8s(pa0, pa1, psc, nxt + aoff);
#pragma unroll
            for (int j = 0; j < QPT4; j++)
                cvt_store4(pbv[j], nxt + AMB + bRowOff + (bq + 16 * j) * 8);
        }
        __syncthreads();
    }

#pragma unroll
    for (int f = 0; f < 2; f++) {
#pragma unroll
        for (int g = 0; g < NF; g++) {
            int r0 = m0 + wm * 32 + f * 16 + (lane >> 2);
            int col = n0 + wn * WN + g * 8 + (lane & 3) * 2;
            float* p = Cout + (size_t)r0 * Nglob + col;
            *(float2*)p = make_float2(acc[f][g][0], acc[f][g][1]);
            *(float2*)(p + 8 * (size_t)Nglob) = make_float2(acc[f][g][2], acc[f][g][3]);
        }
    }
}

// ---------------- down GEMM: single fp16, split-K=4, double-buffered ----------------
__global__ void __launch_bounds__(512, 1) gemm12(const float* __restrict__ Bw)
{
    constexpr int BN = 256;
    constexpr int WN = 64;
    constexpr int NF = 8;
    constexpr int AMB = 128 * 80;
    constexpr int BSTRIDE = BN * 2 + 16;   // 528
    constexpr int BMB = 32 * BSTRIDE;
    constexpr int STG = AMB + BMB;         // 27136
    constexpr int QPT4 = 4;
    constexpr int NG = 512;

    extern __shared__ __align__(128) char dynsmem[];
    uint32_t base = smem_u32(dynsmem);

    float* part[4] = { g_O, g_U, g_U + (size_t)Mm * Dd, g_V };
    float* Cout = part[blockIdx.z];
    int kglob0 = blockIdx.z * 4096;

    int t = threadIdx.x, lane = t & 31, warp = t >> 5;
    int wm = warp & 3, wn = warp >> 2;
    int m0 = blockIdx.y * 128, n0 = blockIdx.x * BN;

    int arow = t >> 2, aq = t & 3;
    const float* aRowBase = g_H + (size_t)(m0 + arow) * 1024 + aq * 8;
    const float* crow = g_c3 + ((m0 + arow) & 127) * 16;
    uint32_t aoff = (uint32_t)arow * 80 + aq * 16;

    int krow = t >> 4;
    int bq = t & 15;
    const float* bRowBase = Bw + (size_t)(kglob0 + krow) * NG + n0;
    uint32_t bRowOff = (uint32_t)krow * BSTRIDE;

    float acc[2][NF][4];
#pragma unroll
    for (int f = 0; f < 2; f++)
#pragma unroll
        for (int g = 0; g < NF; g++)
#pragma unroll
            for (int j = 0; j < 4; j++) acc[f][g][j] = 0.f;

    const int nit = 128;

    float4 pa0, pa1, pbv[QPT4];
    float psc;
    {
        int ktg = kglob0;
        psc = crow[ktg >> 10];
        const float* ar = aRowBase + (ktg & 1023);
        pa0 = *(const float4*)(ar + 0);
        pa1 = *(const float4*)(ar + 4);
#pragma unroll
        for (int j = 0; j < QPT4; j++)
            pbv[j] = *(const float4*)(bRowBase + (bq + 16 * j) * 4);
        cvt_store8s(pa0, pa1, psc, base + aoff);
#pragma unroll
        for (int j = 0; j < QPT4; j++)
            cvt_store4(pbv[j], base + AMB + bRowOff + (bq + 16 * j) * 8);
    }
    __syncthreads();

    for (int it = 0; it < nit; it++) {
        uint32_t cur = base + (uint32_t)(it & 1) * STG;
        uint32_t nxt = base + (uint32_t)((it + 1) & 1) * STG;
        bool more = (it + 1 < nit);

        if (more) {
            int ktn = (it + 1) << 5;
            int ktg = kglob0 + ktn;
            psc = crow[ktg >> 10];
            const float* ar = aRowBase + (ktg & 1023);
            pa0 = *(const float4*)(ar + 0);
            pa1 = *(const float4*)(ar + 4);
            const float* br = bRowBase + (size_t)ktn * NG;
#pragma unroll
            for (int j = 0; j < QPT4; j++)
                pbv[j] = *(const float4*)(br + (bq + 16 * j) * 4);
        }

        uint32_t sA = cur, sB = cur + AMB;
#pragma unroll
        for (int ks = 0; ks < 2; ks++) {
            uint32_t BF[NF][2];
            uint32_t brow = (uint32_t)(ks * 16 + (lane & 15)) * BSTRIDE;
#pragma unroll
            for (int j = 0; j < NF / 2; j++) {
                uint32_t coff = (uint32_t)(wn * WN + j * 16 + ((lane >> 4) & 1) * 8) * 2;
                uint32_t r[4];
                ldsm4t(r, sB + brow + coff);
                BF[2*j][0] = r[0]; BF[2*j][1] = r[1];
                BF[2*j+1][0] = r[2]; BF[2*j+1][1] = r[3];
            }
            uint32_t acolB = (uint32_t)ks * 32 + ((lane >> 4) & 1) * 16;
            uint32_t AF[2][4];
#pragma unroll
            for (int f = 0; f < 2; f++) {
                uint32_t roff = (uint32_t)(wm * 32 + f * 16 + (lane & 15)) * 80 + acolB;
                ldsm4(AF[f], sA + roff);
            }
#pragma unroll
            for (int f = 0; f < 2; f++)
#pragma unroll
                for (int g = 0; g < NF; g++)
                    mmaf16(acc[f][g], AF[f], BF[g]);
        }

        if (more) {
            cvt_store8s(pa0, pa1, psc, nxt + aoff);
#pragma unroll
            for (int j = 0; j < QPT4; j++)
                cvt_store4(pbv[j], nxt + AMB + bRowOff + (bq + 16 * j) * 8);
        }
        __syncthreads();
    }

#pragma unroll
    for (int f = 0; f < 2; f++) {
#pragma unroll
        for (int g = 0; g < NF; g++) {
            int r0 = m0 + wm * 32 + f * 16 + (lane >> 2);
            int col = n0 + wn * WN + g * 8 + (lane & 3) * 2;
            float* p = Cout + (size_t)r0 * NG + col;
            *(float2*)p = make_float2(acc[f][g][0], acc[f][g][1]);
            *(float2*)(p + 8 * NG) = make_float2(acc[f][g][2], acc[f][g][3]);
        }
    }
}

// ---------------- elementwise h ----------------
__global__ void h_kernel(const float* __restrict__ usp, const float* __restrict__ vsp) {
    const float SQRT_D = 22.62741699796952f;
    int i4 = blockIdx.x * blockDim.x + threadIdx.x;
    if (i4 >= Mm * Ff / 4) return;
    int m  = i4 >> 8;
    int f  = (i4 & 255) * 4;
    int l  = m & 127;

    float4 u  = *(const float4*)(g_U   + (size_t)m * Ff + f);
    float4 v  = *(const float4*)(g_V   + (size_t)m * Ff + f);
    float4 ig = *(const float4*)(g_ing + (size_t)l * Ff + f);
    float4 iu = *(const float4*)(g_inu + (size_t)l * Ff + f);
    float4 us = *(const float4*)(usp + f);
    float4 vs = *(const float4*)(vsp + f);

    float4 h;
    { float uu = u.x * ig.x, vv = v.x * iu.x; float zz = fabsf(vs.x) * SQRT_D * vv;
      h.x = (zz / (1.f + expf(-zz))) * (fabsf(us.x) * uu); }
    { float uu = u.y * ig.y, vv = v.y * iu.y; float zz = fabsf(vs.y) * SQRT_D * vv;
      h.y = (zz / (1.f + expf(-zz))) * (fabsf(us.y) * uu); }
    { float uu = u.z * ig.z, vv = v.z * iu.z; float zz = fabsf(vs.z) * SQRT_D * vv;
      h.z = (zz / (1.f + expf(-zz))) * (fabsf(us.z) * uu); }
    { float uu = u.w * ig.w, vv = v.w * iu.w; float zz = fabsf(vs.w) * SQRT_D * vv;
      h.w = (zz / (1.f + expf(-zz))) * (fabsf(us.w) * uu); }
    *(float4*)(g_H + (size_t)m * Ff + f) = h;
}

// ---------------- final: sum 4 split-K partials, apply down-norm, row L2 normalize ----------------
__global__ void out_kernel(float* __restrict__ out) {
    int m = blockIdx.x;
    int t = threadIdx.x;
    int l = m & 127;

    size_t off = (size_t)m * Dd + t * 4;
    float4 p0 = *(const float4*)(g_O + off);
    float4 p1 = *(const float4*)(g_U + off);
    float4 p2 = *(const float4*)(g_U + (size_t)Mm * Dd + off);
    float4 p3 = *(const float4*)(g_V + off);
    float4 iv = *(const float4*)(g_ind + (size_t)l * Dd + t * 4);

    float4 o;
    o.x = ((p0.x + p1.x) + (p2.x + p3.x)) * iv.x;
    o.y = ((p0.y + p1.y) + (p2.y + p3.y)) * iv.y;
    o.z = ((p0.z + p1.z) + (p2.z + p3.z)) * iv.z;
    o.w = ((p0.w + p1.w) + (p2.w + p3.w)) * iv.w;

    float ss = o.x*o.x + o.y*o.y + o.z*o.z + o.w*o.w;
#pragma unroll
    for (int offm = 16; offm > 0; offm >>= 1)
        ss += __shfl_xor_sync(0xffffffffu, ss, offm);

    __shared__ float ws[4];
    if ((t & 31) == 0) ws[t >> 5] = ss;
    __syncthreads();
    float tot = ws[0] + ws[1] + ws[2] + ws[3];
    float sc = 1.f / fmaxf(sqrtf(tot), 1e-12f);

    o.x *= sc; o.y *= sc; o.z *= sc; o.w *= sc;
    *(float4*)(out + off) = o;
}

// ---------------- launch ----------------
extern "C" void kernel_launch(void* const* d_in, const int* in_sizes, int n_in,
                              void* d_out, int out_size) {
    const float* x   = (const float*)d_in[0];
    const float* Wg  = (const float*)d_in[1];
    const float* Wu  = (const float*)d_in[2];
    const float* Wd  = (const float*)d_in[3];
    const float* t1  = (const float*)d_in[4];
    const float* t2  = (const float*)d_in[5];
    const float* t3  = (const float*)d_in[6];
    const float* usp = (const float*)d_in[7];
    const float* vsp = (const float*)d_in[8];
    float* out = (float*)d_out;

    const int DSMEM = 2 * (128 * 80 + 32 * 528);   // 54272
    cudaFuncSetAttribute(gemm11, cudaFuncAttributeMaxDynamicSharedMemorySize, DSMEM);
    cudaFuncSetAttribute(gemm12, cudaFuncAttributeMaxDynamicSharedMemorySize, DSMEM);

    softmax_kernel<<<3, 128>>>(t1, t2, t3);
    gram_kernel<<<dim3(32, 3), 256>>>(Wg, Wu, Wd);
    norm_kernel<<<dim3(8, 16, 3), 128>>>();

    // U and V fused (z=0 -> U, z=1 -> V): BN=256, 128 blocks, 512 threads
    gemm11<<<dim3(4, 16, 2), 512, DSMEM>>>(x, Wg, Wu, 512, 9, 8192, 1024);
    // h = silu(vs*v) * (us*u)
    h_kernel<<<2048, 256>>>(usp, vsp);
    // O partials: split-K=4 -> g_O, g_U, g_U+1M, g_V
    gemm12<<<dim3(2, 16, 4), 512, DSMEM>>>(Wd);
    // final: sum 4 partials + normalize
    out_kernel<<<2048, 128>>>(out);
}